// round 9
// baseline (speedup 1.0000x reference)
#include <cuda_runtime.h>
#include <cuda_bf16.h>
#include <math_constants.h>
#include <cstdint>

#define MAXN 100000
#define MAXE 1600000
#define IN_DIM 128
#define EDGE_DIM 16
#define NH 4
#define OUT_H 64
#define F_MLP 272   // 2*128+16

// ---------------- device scratch ----------------------------------------------
__device__ int   g_rowptr[MAXN + 1];
__device__ float g_attn12[(size_t)MAXN * 8];
__device__ float g_lg[(size_t)MAXE * 4];
__device__ float g_h1[(size_t)MAXN * NH * OUT_H];      // [n][h][64] = [n][256]
__device__ float g_sum[NH * OUT_H];
__device__ float g_sqsum[NH * OUT_H];
__device__ float g_a[NH * OUT_H];
__device__ float g_c[NH * OUT_H];
// bf16 hi/lo pre-split data
__device__ __nv_bfloat16 g_xhi[(size_t)MAXN * 128];
__device__ __nv_bfloat16 g_xlo[(size_t)MAXN * 128];
__device__ __nv_bfloat16 g_obhi[(size_t)MAXN * NH * 128];
__device__ __nv_bfloat16 g_oblo[(size_t)MAXN * NH * 128];
__device__ __nv_bfloat16 g_xehi[(size_t)MAXN * NH * 16];
__device__ __nv_bfloat16 g_xelo[(size_t)MAXN * NH * 16];
__device__ __nv_bfloat16 g_w1s[(size_t)NH * 2 * OUT_H * F_MLP];  // [h][pass][o][272]
__device__ __nv_bfloat16 g_w2s[(size_t)NH * 2 * OUT_H * OUT_H];  // [h][pass][p][64]

// ---------------- helpers ------------------------------------------------------
__device__ __forceinline__ uint32_t smem_u32(const void* p) {
    uint32_t a;
    asm("{ .reg .u64 t; cvta.to.shared.u64 t, %1; cvt.u32.u64 %0, t; }" : "=r"(a) : "l"(p));
    return a;
}
__device__ __forceinline__ void cpa16(uint32_t dst, const void* src) {
    asm volatile("cp.async.cg.shared.global [%0], [%1], 16;" :: "r"(dst), "l"(src));
}
#define CPCOMMIT() asm volatile("cp.async.commit_group;" ::: "memory")
#define CPWAIT0()  asm volatile("cp.async.wait_group 0;" ::: "memory")
#define CPWAIT1()  asm volatile("cp.async.wait_group 1;" ::: "memory")
#define CPWAIT()   asm volatile("cp.async.commit_group;\n\tcp.async.wait_group 0;" ::: "memory")

__device__ __forceinline__ void ldsm4(uint32_t* r, uint32_t a) {
    asm volatile("ldmatrix.sync.aligned.m8n8.x4.shared.b16 {%0,%1,%2,%3}, [%4];"
        : "=r"(r[0]), "=r"(r[1]), "=r"(r[2]), "=r"(r[3]) : "r"(a));
}
__device__ __forceinline__ void ldsm2(uint32_t* r, uint32_t a) {
    asm volatile("ldmatrix.sync.aligned.m8n8.x2.shared.b16 {%0,%1}, [%2];"
        : "=r"(r[0]), "=r"(r[1]) : "r"(a));
}
__device__ __forceinline__ void mma_bf16(float* c, const uint32_t* a,
                                         uint32_t b0, uint32_t b1) {
    asm volatile("mma.sync.aligned.m16n8k16.row.col.f32.bf16.bf16.f32 "
        "{%0,%1,%2,%3}, {%4,%5,%6,%7}, {%8,%9}, {%0,%1,%2,%3};"
        : "+f"(c[0]), "+f"(c[1]), "+f"(c[2]), "+f"(c[3])
        : "r"(a[0]), "r"(a[1]), "r"(a[2]), "r"(a[3]), "r"(b0), "r"(b1));
}

template<int KSTEPS, int SA, int SB>
__device__ __forceinline__ void mma_block(float c[2][4][4], uint32_t aBase,
                                          uint32_t bBase, int lane) {
    uint32_t aRow = aBase + (uint32_t)(((lane & 15) * SA + ((lane >> 4) << 3)) * 2);
    uint32_t bRow = bBase + (uint32_t)(((lane & 7) * SB + (((lane >> 3) & 1) << 3)) * 2);
#pragma unroll
    for (int ks = 0; ks < KSTEPS; ks++) {
        uint32_t a0[4], a1[4];
        ldsm4(a0, aRow + ks * 32);
        ldsm4(a1, aRow + 16 * SA * 2 + ks * 32);
#pragma unroll
        for (int ni = 0; ni < 4; ni++) {
            uint32_t b[2];
            ldsm2(b, bRow + ni * 8 * SB * 2 + ks * 32);
            mma_bf16(c[0][ni], a0, b[0], b[1]);
            mma_bf16(c[1][ni], a1, b[0], b[1]);
        }
    }
}

// split fp32 float4 -> bf16 hi pair-words + lo pair-words
__device__ __forceinline__ void split4(float4 v, uint32_t& hi01, uint32_t& hi23,
                                       uint32_t& lo01, uint32_t& lo23) {
    uint32_t b0 = __float_as_uint(v.x), b1 = __float_as_uint(v.y);
    uint32_t b2 = __float_as_uint(v.z), b3 = __float_as_uint(v.w);
    hi01 = __byte_perm(b0, b1, 0x7632);
    hi23 = __byte_perm(b2, b3, 0x7632);
    float l0 = v.x - __uint_as_float(b0 & 0xffff0000u);
    float l1 = v.y - __uint_as_float(b1 & 0xffff0000u);
    float l2 = v.z - __uint_as_float(b2 & 0xffff0000u);
    float l3 = v.w - __uint_as_float(b3 & 0xffff0000u);
    __nv_bfloat162 p01 = __floats2bfloat162_rn(l0, l1);
    __nv_bfloat162 p23 = __floats2bfloat162_rn(l2, l3);
    lo01 = *reinterpret_cast<uint32_t*>(&p01);
    lo23 = *reinterpret_cast<uint32_t*>(&p23);
}

// ---------------- K0: CSR row pointers ----------------------------------------
__global__ void k_rowptr(const int* __restrict__ row, int n, int e) {
    int i = blockIdx.x * blockDim.x + threadIdx.x;
    if (i > n) return;
    int lo = 0, hi = e;
    while (lo < hi) { int mid = (lo + hi) >> 1; if (row[mid] < i) lo = mid + 1; else hi = mid; }
    g_rowptr[i] = lo;
}

// ---------------- K1: per-node attention logits -------------------------------
__global__ void k_nodelogits(const float* __restrict__ x, const float* __restrict__ a1w,
                             const float* __restrict__ a2w, int n) {
    __shared__ float sw[8 * 128];
    int tid = threadIdx.x;
    for (int i = tid; i < 512; i += 256) { sw[i] = a1w[i]; sw[512 + i] = a2w[i]; }
    __syncthreads();
    int warp = tid >> 5, lane = tid & 31;
    int nd = blockIdx.x * 8 + warp;
    if (nd >= n) return;
    float4 xv = *(const float4*)(x + (size_t)nd * 128 + lane * 4);
#pragma unroll
    for (int k = 0; k < 8; k++) {
        float4 wv = *(const float4*)(sw + k * 128 + lane * 4);
        float p = xv.x * wv.x + xv.y * wv.y + xv.z * wv.z + xv.w * wv.w;
        p += __shfl_xor_sync(0xffffffffu, p, 16);
        p += __shfl_xor_sync(0xffffffffu, p, 8);
        p += __shfl_xor_sync(0xffffffffu, p, 4);
        p += __shfl_xor_sync(0xffffffffu, p, 2);
        p += __shfl_xor_sync(0xffffffffu, p, 1);
        if (lane == 0) g_attn12[(size_t)nd * 8 + k] = p;
    }
}

// ---------------- K_pre: pre-split w1/w2 to bf16 hi/lo; zero stats ------------
__global__ void k_pre(const float* __restrict__ w1, const float* __restrict__ w2) {
    int h = blockIdx.x, tid = threadIdx.x;   // 4 blocks x 256
    for (int i = tid; i < OUT_H * 68; i += 256) {
        int o = i / 68, f = (i - o * 68) * 4;
        float4 v = *(const float4*)(w1 + ((size_t)h * OUT_H + o) * F_MLP + f);
        uint32_t h01, h23, l01, l23;
        split4(v, h01, h23, l01, l23);
        *(uint2*)(g_w1s + ((size_t)(h * 2 + 0) * OUT_H + o) * F_MLP + f) = make_uint2(h01, h23);
        *(uint2*)(g_w1s + ((size_t)(h * 2 + 1) * OUT_H + o) * F_MLP + f) = make_uint2(l01, l23);
    }
    for (int i = tid; i < OUT_H * 16; i += 256) {
        int p = i >> 4, f = (i & 15) * 4;
        float4 v = *(const float4*)(w2 + (size_t)h * 4096 + p * 64 + f);
        uint32_t h01, h23, l01, l23;
        split4(v, h01, h23, l01, l23);
        *(uint2*)(g_w2s + ((size_t)(h * 2 + 0) * OUT_H + p) * 64 + f) = make_uint2(h01, h23);
        *(uint2*)(g_w2s + ((size_t)(h * 2 + 1) * OUT_H + p) * 64 + f) = make_uint2(l01, l23);
    }
    if (h == 0) { g_sum[tid] = 0.f; g_sqsum[tid] = 0.f; }
}

// ---------------- K_xsplit: pre-split x ---------------------------------------
__global__ void k_xsplit(const float* __restrict__ x, int n) {
    size_t i = (size_t)blockIdx.x * blockDim.x + threadIdx.x;
    if (i * 4 >= (size_t)n * 128) return;
    float4 v = *(const float4*)(x + i * 4);
    uint32_t h01, h23, l01, l23;
    split4(v, h01, h23, l01, l23);
    *(uint2*)(g_xhi + i * 4) = make_uint2(h01, h23);
    *(uint2*)(g_xlo + i * 4) = make_uint2(l01, l23);
}

// ---------------- K2: edge softmax + aggregation, cp.async staged -------------
__device__ __forceinline__ void edge_logits(const float* __restrict__ ea,
                                            const float* s_aew, int e2, int ci,
                                            const float* a1h, float* lg) {
    const float4* ep = (const float4*)(ea + (size_t)e2 * 16);
    float4 q0 = ep[0], q1 = ep[1], q2 = ep[2], q3 = ep[3];
    float4 a2v = *(const float4*)(g_attn12 + (size_t)ci * 8 + 4);
    float a2a[4] = {a2v.x, a2v.y, a2v.z, a2v.w};
#pragma unroll
    for (int h = 0; h < 4; h++) {
        const float* wq = s_aew + h * 16;
        float d = q0.x * wq[0] + q0.y * wq[1] + q0.z * wq[2] + q0.w * wq[3]
                + q1.x * wq[4] + q1.y * wq[5] + q1.z * wq[6] + q1.w * wq[7]
                + q2.x * wq[8] + q2.y * wq[9] + q2.z * wq[10] + q2.w * wq[11]
                + q3.x * wq[12] + q3.y * wq[13] + q3.z * wq[14] + q3.w * wq[15];
        lg[h] = (a1h[h] + a2a[h] + d) * 0.125f;
    }
}

// smem: stages 8 warps x 2 bufs x 8 edges x 512B = 65536; swp 4096; scp 1024; aew 256
#define KE_SMEM (65536 + 4096 + 1024 + 256)
__global__ void __launch_bounds__(256) k_edge(const float* __restrict__ x,
                                              const int* __restrict__ col,
                                              const float* __restrict__ ea,
                                              const float* __restrict__ aew, int n) {
    extern __shared__ char ksm[];
    float* s_wall = (float*)(ksm + 65536);           // [8][32][4]
    int*   s_call = (int*)(ksm + 65536 + 4096);      // [8][32]
    float* s_aew  = (float*)(ksm + 65536 + 5120);    // [64]
    uint32_t sb = smem_u32(ksm);
    int tid = threadIdx.x;
    if (tid < 64) s_aew[tid] = aew[tid];
    __syncthreads();
    int warp = tid >> 5, lane = tid & 31;
    int nd = blockIdx.x * 8 + warp;
    if (nd >= n) return;
    int start = g_rowptr[nd], end = g_rowptr[nd + 1];
    int deg = end - start;
    float a1h[4];
    {
        float4 a1v = *(const float4*)(g_attn12 + (size_t)nd * 8);
        a1h[0] = a1v.x; a1h[1] = a1v.y; a1h[2] = a1v.z; a1h[3] = a1v.w;
    }
    float* swp = s_wall + warp * 128;
    int*   scp = s_call + warp * 32;
    uint32_t stage = sb + warp * 8192;               // 2 bufs x 4096 B
    const float* stagef = (const float*)ksm + warp * 2048;

    float m[4], inv[4];

    if (deg <= 32) {
        int e2 = start + lane;
        bool have = (e2 < end);
        float lg[4] = {-CUDART_INF_F, -CUDART_INF_F, -CUDART_INF_F, -CUDART_INF_F};
        int ci = 0;
        if (have) { ci = col[e2]; edge_logits(ea, s_aew, e2, ci, a1h, lg); }
#pragma unroll
        for (int h = 0; h < 4; h++) {
            float mm = lg[h];
#pragma unroll
            for (int off = 16; off >= 1; off >>= 1)
                mm = fmaxf(mm, __shfl_xor_sync(0xffffffffu, mm, off));
            float ex = have ? __expf(lg[h] - mm) : 0.f;
            float ssum = ex;
#pragma unroll
            for (int off = 16; off >= 1; off >>= 1)
                ssum += __shfl_xor_sync(0xffffffffu, ssum, off);
            float iv = 1.f / (ssum + 1e-16f);
            swp[lane * 4 + h] = ex * iv;
        }
        scp[lane] = ci;
        m[0] = 0.f;
    } else {
        float mm[4] = {-CUDART_INF_F, -CUDART_INF_F, -CUDART_INF_F, -CUDART_INF_F};
        float s[4] = {0.f, 0.f, 0.f, 0.f};
        for (int base = start; base < end; base += 32) {
            int e2 = base + lane;
            if (e2 < end) {
                int ci = col[e2];
                float lg[4];
                edge_logits(ea, s_aew, e2, ci, a1h, lg);
                *(float4*)(g_lg + (size_t)e2 * 4) = make_float4(lg[0], lg[1], lg[2], lg[3]);
#pragma unroll
                for (int h = 0; h < 4; h++) {
                    if (lg[h] > mm[h]) { s[h] = s[h] * __expf(mm[h] - lg[h]) + 1.f; mm[h] = lg[h]; }
                    else               { s[h] += __expf(lg[h] - mm[h]); }
                }
            }
        }
#pragma unroll
        for (int off = 16; off >= 1; off >>= 1) {
#pragma unroll
            for (int h = 0; h < 4; h++) {
                float om = __shfl_xor_sync(0xffffffffu, mm[h], off);
                float os = __shfl_xor_sync(0xffffffffu, s[h], off);
                float nm = fmaxf(mm[h], om);
                float t = (s[h] > 0.f ? s[h] * __expf(mm[h] - nm) : 0.f)
                        + (os > 0.f ? os * __expf(om - nm) : 0.f);
                mm[h] = nm; s[h] = t;
            }
        }
#pragma unroll
        for (int h = 0; h < 4; h++) { m[h] = mm[h]; inv[h] = 1.f / (s[h] + 1e-16f); }
    }

    float4 acc[4];
#pragma unroll
    for (int h = 0; h < 4; h++) acc[h] = make_float4(0.f, 0.f, 0.f, 0.f);
    float acce[4] = {0.f, 0.f, 0.f, 0.f};

    for (int base = start; base < end; base += 32) {
        int cnt = min(32, end - base);
        if (deg > 32) {
            int e2 = base + lane;
            __syncwarp();
            if (e2 < end) {
                float4 lgv = *(const float4*)(g_lg + (size_t)e2 * 4);
                swp[lane * 4 + 0] = __expf(lgv.x - m[0]) * inv[0];
                swp[lane * 4 + 1] = __expf(lgv.y - m[1]) * inv[1];
                swp[lane * 4 + 2] = __expf(lgv.z - m[2]) * inv[2];
                swp[lane * 4 + 3] = __expf(lgv.w - m[3]) * inv[3];
                scp[lane] = col[e2];
            }
        }
        __syncwarp();
        // prologue: stage 0 of this chunk
        {
            int lim = min(8, cnt);
            for (int k = 0; k < lim; k++) {
                int cj = scp[k];
                cpa16(stage + k * 512 + lane * 16, x + (size_t)cj * 128 + lane * 4);
            }
            CPCOMMIT();
        }
        for (int s = 0; s < cnt; s += 8) {
            if (s + 8 < cnt) {
                uint32_t nb = stage + (((s >> 3) + 1) & 1) * 4096;
                int lim = min(8, cnt - s - 8);
                for (int k = 0; k < lim; k++) {
                    int cj = scp[s + 8 + k];
                    cpa16(nb + k * 512 + lane * 16, x + (size_t)cj * 128 + lane * 4);
                }
                CPCOMMIT();
                CPWAIT1();
            } else {
                CPWAIT0();
            }
            int lim = min(8, cnt - s);
            const float* bufp = stagef + ((s >> 3) & 1) * 1024;
#pragma unroll 4
            for (int j = 0; j < lim; j++) {
                float4 wv = *(const float4*)(swp + (s + j) * 4);
                float4 xv = *(const float4*)(bufp + j * 128 + lane * 4);
                acc[0].x += wv.x * xv.x; acc[0].y += wv.x * xv.y; acc[0].z += wv.x * xv.z; acc[0].w += wv.x * xv.w;
                acc[1].x += wv.y * xv.x; acc[1].y += wv.y * xv.y; acc[1].z += wv.y * xv.z; acc[1].w += wv.y * xv.w;
                acc[2].x += wv.z * xv.x; acc[2].y += wv.z * xv.y; acc[2].z += wv.z * xv.z; acc[2].w += wv.z * xv.w;
                acc[3].x += wv.w * xv.x; acc[3].y += wv.w * xv.y; acc[3].z += wv.w * xv.z; acc[3].w += wv.w * xv.w;
                if (lane < 16) {
                    float eav = ea[(size_t)(base + s + j) * 16 + lane];
                    acce[0] += wv.x * eav; acce[1] += wv.y * eav;
                    acce[2] += wv.z * eav; acce[3] += wv.w * eav;
                }
            }
        }
    }
    // epilogue: write xobj / xe as bf16 hi/lo
#pragma unroll
    for (int h = 0; h < 4; h++) {
        uint32_t h01, h23, l01, l23;
        split4(acc[h], h01, h23, l01, l23);
        size_t off = ((size_t)nd * 4 + h) * 128 + lane * 4;
        *(uint2*)(g_obhi + off) = make_uint2(h01, h23);
        *(uint2*)(g_oblo + off) = make_uint2(l01, l23);
    }
    if (lane < 16) {
#pragma unroll
        for (int h = 0; h < 4; h++) {
            float v = acce[h];
            uint32_t b = __float_as_uint(v);
            size_t off = ((size_t)nd * 4 + h) * 16 + lane;
            g_xehi[off] = __ushort_as_bfloat16((unsigned short)(b >> 16));
            g_xelo[off] = __float2bfloat16(v - __uint_as_float(b & 0xffff0000u));
        }
    }
}

// ---------------- K3: MLP layer 1 via mma.sync, streamed buffers --------------
// smem: A[128][280] bf16 (71680 B) + B[64][280] bf16 (35840 B) = 107520 -> 2 CTA/SM
#define SA1 280
#define SMB1 71680
#define MLP1_SMEM 107520
__global__ void __launch_bounds__(256, 2) k_mlp1h(const float* __restrict__ b1, int n) {
    extern __shared__ char smem[];
    uint32_t sb = smem_u32(smem);
    int tid = threadIdx.x, lane = tid & 31, wid = tid >> 5;
    int h = blockIdx.y;
    int n0 = blockIdx.x * 128;

    float c4[2][4][4] = {};
    int wm = wid & 3, wn = wid >> 2;
    uint32_t aB = sb + wm * 32 * (SA1 * 2);
    uint32_t bB = sb + SMB1 + wn * 32 * (SA1 * 2);

    // ---- fill A (hi) + B (hi) ----
    {
        for (int i = tid; i < 128 * 34; i += 256) {
            int r = i / 34, c = i - r * 34;
            int nd = n0 + r;
            uint32_t dst = sb + r * 560 + c * 16;
            if (nd < n) {
                const char* src;
                if (c < 16)      src = (const char*)(g_xhi + (size_t)nd * 128) + c * 16;
                else if (c < 32) src = (const char*)(g_obhi + ((size_t)nd * 4 + h) * 128) + (c - 16) * 16;
                else             src = (const char*)(g_xehi + ((size_t)nd * 4 + h) * 16) + (c - 32) * 16;
                cpa16(dst, src);
            } else {
                *(uint4*)(smem + r * 560 + c * 16) = make_uint4(0, 0, 0, 0);
            }
        }
        const __nv_bfloat16* ws = g_w1s + (size_t)(h * 2 + 0) * OUT_H * F_MLP;
        for (int i = tid; i < 64 * 34; i += 256) {
            int r = i / 34, c = i - r * 34;
            cpa16(sb + SMB1 + r * 560 + c * 16, (const char*)(ws + (size_t)r * F_MLP) + c * 16);
        }
        CPWAIT();
        __syncthreads();
    }
    mma_block<17, SA1, SA1>(c4, aB, bB, lane);      // A_hi * B_hi
    __syncthreads();
    // ---- refill B (lo) ----
    {
        const __nv_bfloat16* ws = g_w1s + (size_t)(h * 2 + 1) * OUT_H * F_MLP;
        for (int i = tid; i < 64 * 34; i += 256) {
            int r = i / 34, c = i - r * 34;
            cpa16(sb + SMB1 + r * 560 + c * 16, (const char*)(ws + (size_t)r * F_MLP) + c * 16);
        }
        CPWAIT();
        __syncthreads();
    }
    mma_block<17, SA1, SA1>(c4, aB, bB, lane);      // A_hi * B_lo
    __syncthreads();
    // ---- refill A (lo) + B (hi) ----
    {
        for (int i = tid; i < 128 * 34; i += 256) {
            int r = i / 34, c = i - r * 34;
            int nd = n0 + r;
            uint32_t dst = sb + r * 560 + c * 16;
            if (nd < n) {
                const char* src;
                if (c < 16)      src = (const char*)(g_xlo + (size_t)nd * 128) + c * 16;
                else if (c < 32) src = (const char*)(g_oblo + ((size_t)nd * 4 + h) * 128) + (c - 16) * 16;
                else             src = (const char*)(g_xelo + ((size_t)nd * 4 + h) * 16) + (c - 32) * 16;
                cpa16(dst, src);
            } else {
                *(uint4*)(smem + r * 560 + c * 16) = make_uint4(0, 0, 0, 0);
            }
        }
        const __nv_bfloat16* ws = g_w1s + (size_t)(h * 2 + 0) * OUT_H * F_MLP;
        for (int i = tid; i < 64 * 34; i += 256) {
            int r = i / 34, c = i - r * 34;
            cpa16(sb + SMB1 + r * 560 + c * 16, (const char*)(ws + (size_t)r * F_MLP) + c * 16);
        }
        CPWAIT();
        __syncthreads();
    }
    mma_block<17, SA1, SA1>(c4, aB, bB, lane);      // A_lo * B_hi

    // ---- epilogue: bias + ReLU -> g_h1, fold BN partial stats ----
    __syncthreads();                                  // smem reuse for reduction
    float* sred = (float*)smem;                       // [128]: sum[64], sq[64]
    if (tid < 128) sred[tid] = 0.f;
    __syncthreads();

    const float* bb = b1 + h * 64;
    int g = lane >> 2, tc2 = 2 * (lane & 3);
#pragma unroll
    for (int mi = 0; mi < 2; mi++) {
#pragma unroll
        for (int ni = 0; ni < 4; ni++) {
            int colo = wn * 32 + ni * 8 + tc2;
            float2 bv = *(const float2*)(bb + colo);
            int ndr = n0 + wm * 32 + mi * 16 + g;
            float* dst = g_h1 + (size_t)ndr * 256 + h * 64 + colo;
            if (ndr < n) {
                float v0 = fmaxf(c4[mi][ni][0] + bv.x, 0.f);
                float v1 = fmaxf(c4[mi][ni][1] + bv.y, 0.f);
                *(float2*)dst = make_float2(v0, v1);
                atomicAdd(&sred[colo], v0);     atomicAdd(&sred[64 + colo], v0 * v0);
                atomicAdd(&sred[colo + 1], v1); atomicAdd(&sred[64 + colo + 1], v1 * v1);
            }
            if (ndr + 8 < n) {
                float v2 = fmaxf(c4[mi][ni][2] + bv.x, 0.f);
                float v3 = fmaxf(c4[mi][ni][3] + bv.y, 0.f);
                *(float2*)(dst + 8 * 256) = make_float2(v2, v3);
                atomicAdd(&sred[colo], v2);     atomicAdd(&sred[64 + colo], v2 * v2);
                atomicAdd(&sred[colo + 1], v3); atomicAdd(&sred[64 + colo + 1], v3 * v3);
            }
        }
    }
    __syncthreads();
    if (tid < 64) {
        atomicAdd(&g_sum[h * 64 + tid], sred[tid]);
        atomicAdd(&g_sqsum[h * 64 + tid], sred[64 + tid]);
    }
}

// ---------------- K4: finalize BN stats ---------------------------------------
__global__ void k_stats(const float* __restrict__ gamma, const float* __restrict__ beta, int n) {
    int i = threadIdx.x;   // 256
    float inv_n = 1.f / (float)n;
    float mu = g_sum[i] * inv_n;
    float var = g_sqsum[i] * inv_n - mu * mu;
    float r = rsqrtf(var + 1e-5f);
    float a = r * gamma[i];
    g_a[i] = a;
    g_c[i] = beta[i] - mu * a;
}

// ---------------- K5: BN apply + MLP layer 2 via mma.sync ---------------------
#define SA2 72
#define A2HI 0
#define A2LO (128 * SA2 * 2)                 // 18432
#define B2HI (2 * 128 * SA2 * 2)             // 36864
#define B2LO (B2HI + 64 * SA2 * 2)           // 46080
#define MLP2_SMEM (B2LO + 64 * SA2 * 2)      // 55296
__global__ void __launch_bounds__(256) k_mlp2h(const float* __restrict__ b2,
                                               float* __restrict__ out, int n) {
    extern __shared__ char smem[];
    uint32_t sb = smem_u32(smem);
    int tid = threadIdx.x, lane = tid & 31, wid = tid >> 5;
    int h = blockIdx.y;
    int n0 = blockIdx.x * 128;

    // fill B hi/lo via cp.async from pre-split w2
    {
        const char* wh = (const char*)(g_w2s + (size_t)(h * 2 + 0) * OUT_H * 64);
        const char* wl = (const char*)(g_w2s + (size_t)(h * 2 + 1) * OUT_H * 64);
        for (int i = tid; i < 64 * 8; i += 256) {
            int r = i >> 3, c = i & 7;
            cpa16(sb + B2HI + r * 144 + c * 16, wh + (size_t)r * 128 + c * 16);
            cpa16(sb + B2LO + r * 144 + c * 16, wl + (size_t)r * 128 + c * 16);
        }
    }
    // fill A: BN-applied h1 (inline split; K=64 only)
    for (int i = tid; i < 128 * 16; i += 256) {
        int nl = i >> 4, f = (i & 15) * 4;
        int nd = n0 + nl;
        float4 v = make_float4(0.f, 0.f, 0.f, 0.f);
        if (nd < n) {
            float4 hv = *(const float4*)(g_h1 + (size_t)nd * 256 + h * 64 + f);
            float4 av = *(const float4*)(g_a + h * 64 + f);
            float4 cv = *(const float4*)(g_c + h * 64 + f);
            v = make_float4(hv.x * av.x + cv.x, hv.y * av.y + cv.y,
                            hv.z * av.z + cv.z, hv.w * av.w + cv.w);
        }
        uint32_t h01, h23, l01, l23;
        split4(v, h01, h23, l01, l23);
        *(uint2*)(smem + A2HI + (nl * SA2 + f) * 2) = make_uint2(h01, h23);
        *(uint2*)(smem + A2LO + (nl * SA2 + f) * 2) = make_uint2(l01, l23);
    }
    CPWAIT();
    __syncthreads();

    float c4[2][4][4] = {};
    int wm = wid & 3, wn = wid >> 2;
    uint32_t aH = sb + A2HI + wm * 32 * SA2 * 2;
    uint32_t aL = sb + A2LO + wm * 32 * SA2 * 2;
    uint32_t bH = sb + B2HI + wn * 32 * SA2 * 2;
    uint32_t bL = sb + B2LO + wn * 32 * SA2 * 2;
    mma_block<4, SA2, SA2>(c4, aH, bH, lane);
    mma_block<4, SA2, SA2>(c4, aH, bL, lane);
    mma_block<4, SA2, SA2>(c4, aL, bH, lane);

    // epilogue: bias -> out
    const float* bb = b2 + h * 64;
    int g = lane >> 2, tc2 = 2 * (lane & 3);
#pragma unroll
    for (int mi = 0; mi < 2; mi++) {
#pragma unroll
        for (int ni = 0; ni < 4; ni++) {
            int colo = wn * 32 + ni * 8 + tc2;
            float2 bv = *(const float2*)(bb + colo);
            int ndr = n0 + wm * 32 + mi * 16 + g;
            float* dst = out + (size_t)ndr * 256 + h * 64 + colo;
            if (ndr < n)
                *(float2*)dst = make_float2(c4[mi][ni][0] + bv.x, c4[mi][ni][1] + bv.y);
            if (ndr + 8 < n)
                *(float2*)(dst + 8 * 256) =
                    make_float2(c4[mi][ni][2] + bv.x, c4[mi][ni][3] + bv.y);
        }
    }
}

// ---------------- launch ------------------------------------------------------
extern "C" void kernel_launch(void* const* d_in, const int* in_sizes, int n_in,
                              void* d_out, int out_size) {
    const float* x     = (const float*)d_in[0];
    const int*   row   = (const int*)d_in[1];
    const int*   col   = (const int*)d_in[2];
    const float* ea    = (const float*)d_in[3];
    const float* a1w   = (const float*)d_in[4];
    const float* a2w   = (const float*)d_in[5];
    const float* aew   = (const float*)d_in[6];
    const float* w1    = (const float*)d_in[7];
    const float* b1    = (const float*)d_in[8];
    const float* gamma = (const float*)d_in[9];
    const float* beta  = (const float*)d_in[10];
    const float* w2    = (const float*)d_in[11];
    const float* b2    = (const float*)d_in[12];
    float* out = (float*)d_out;

    int n = in_sizes[0] / IN_DIM;
    int e = in_sizes[1];

    cudaFuncSetAttribute(k_edge, cudaFuncAttributeMaxDynamicSharedMemorySize, KE_SMEM);
    cudaFuncSetAttribute(k_mlp1h, cudaFuncAttributeMaxDynamicSharedMemorySize, MLP1_SMEM);
    cudaFuncSetAttribute(k_mlp2h, cudaFuncAttributeMaxDynamicSharedMemorySize, MLP2_SMEM);

    k_rowptr<<<(n + 256) / 256, 256>>>(row, n, e);
    k_nodelogits<<<(n + 7) / 8, 256>>>(x, a1w, a2w, n);
    k_pre<<<4, 256>>>(w1, w2);
    k_xsplit<<<(n * 32 + 255) / 256, 256>>>(x, n);
    k_edge<<<(n + 7) / 8, 256, KE_SMEM>>>(x, col, ea, aew, n);
    dim3 g3((n + 127) / 128, 4);
    k_mlp1h<<<g3, 256, MLP1_SMEM>>>(b1, n);
    k_stats<<<1, 256>>>(gamma, beta, n);
    k_mlp2h<<<g3, 256, MLP2_SMEM>>>(b2, out, n);
}

// round 11
// speedup vs baseline: 1.1787x; 1.1787x over previous
#include <cuda_runtime.h>
#include <cuda_bf16.h>
#include <math_constants.h>
#include <cstdint>

#define MAXN 100000
#define MAXE 1600000
#define IN_DIM 128
#define EDGE_DIM 16
#define NH 4
#define OUT_H 64
#define F_MLP 272   // 2*128+16

// ---------------- device scratch ----------------------------------------------
__device__ int   g_rowptr[MAXN + 1];
__device__ float g_attn12[(size_t)MAXN * 8];
__device__ float g_lg[(size_t)MAXE * 4];
__device__ float g_h1[(size_t)MAXN * NH * OUT_H];      // [n][h][64] = [n][256]
__device__ float g_sum[NH * OUT_H];
__device__ float g_sqsum[NH * OUT_H];
__device__ float g_a[NH * OUT_H];
__device__ float g_c[NH * OUT_H];
// bf16 hi/lo pre-split data
__device__ __nv_bfloat16 g_xhi[(size_t)MAXN * 128];
__device__ __nv_bfloat16 g_xlo[(size_t)MAXN * 128];
__device__ __nv_bfloat16 g_obhi[(size_t)MAXN * NH * 128];
__device__ __nv_bfloat16 g_oblo[(size_t)MAXN * NH * 128];
__device__ __nv_bfloat16 g_xehi[(size_t)MAXN * NH * 16];
__device__ __nv_bfloat16 g_xelo[(size_t)MAXN * NH * 16];
__device__ __nv_bfloat16 g_w1s[(size_t)NH * 2 * OUT_H * F_MLP];  // [h][pass][o][272]
__device__ __nv_bfloat16 g_w2s[(size_t)NH * 2 * OUT_H * OUT_H];  // [h][pass][p][64]

// ---------------- helpers ------------------------------------------------------
__device__ __forceinline__ uint32_t smem_u32(const void* p) {
    uint32_t a;
    asm("{ .reg .u64 t; cvta.to.shared.u64 t, %1; cvt.u32.u64 %0, t; }" : "=r"(a) : "l"(p));
    return a;
}
__device__ __forceinline__ void cpa16(uint32_t dst, const void* src) {
    asm volatile("cp.async.cg.shared.global [%0], [%1], 16;" :: "r"(dst), "l"(src));
}
#define CPWAIT() asm volatile("cp.async.commit_group;\n\tcp.async.wait_group 0;" ::: "memory")

__device__ __forceinline__ void ldsm4(uint32_t* r, uint32_t a) {
    asm volatile("ldmatrix.sync.aligned.m8n8.x4.shared.b16 {%0,%1,%2,%3}, [%4];"
        : "=r"(r[0]), "=r"(r[1]), "=r"(r[2]), "=r"(r[3]) : "r"(a));
}
__device__ __forceinline__ void ldsm2(uint32_t* r, uint32_t a) {
    asm volatile("ldmatrix.sync.aligned.m8n8.x2.shared.b16 {%0,%1}, [%2];"
        : "=r"(r[0]), "=r"(r[1]) : "r"(a));
}
__device__ __forceinline__ void mma_bf16(float* c, const uint32_t* a,
                                         uint32_t b0, uint32_t b1) {
    asm volatile("mma.sync.aligned.m16n8k16.row.col.f32.bf16.bf16.f32 "
        "{%0,%1,%2,%3}, {%4,%5,%6,%7}, {%8,%9}, {%0,%1,%2,%3};"
        : "+f"(c[0]), "+f"(c[1]), "+f"(c[2]), "+f"(c[3])
        : "r"(a[0]), "r"(a[1]), "r"(a[2]), "r"(a[3]), "r"(b0), "r"(b1));
}

template<int KSTEPS, int SA, int SB>
__device__ __forceinline__ void mma_block(float c[2][4][4], uint32_t aBase,
                                          uint32_t bBase, int lane) {
    uint32_t aRow = aBase + (uint32_t)(((lane & 15) * SA + ((lane >> 4) << 3)) * 2);
    uint32_t bRow = bBase + (uint32_t)(((lane & 7) * SB + (((lane >> 3) & 1) << 3)) * 2);
#pragma unroll
    for (int ks = 0; ks < KSTEPS; ks++) {
        uint32_t a0[4], a1[4];
        ldsm4(a0, aRow + ks * 32);
        ldsm4(a1, aRow + 16 * SA * 2 + ks * 32);
#pragma unroll
        for (int ni = 0; ni < 4; ni++) {
            uint32_t b[2];
            ldsm2(b, bRow + ni * 8 * SB * 2 + ks * 32);
            mma_bf16(c[0][ni], a0, b[0], b[1]);
            mma_bf16(c[1][ni], a1, b[0], b[1]);
        }
    }
}

// split fp32 float4 -> bf16 hi pair-words + lo pair-words
__device__ __forceinline__ void split4(float4 v, uint32_t& hi01, uint32_t& hi23,
                                       uint32_t& lo01, uint32_t& lo23) {
    uint32_t b0 = __float_as_uint(v.x), b1 = __float_as_uint(v.y);
    uint32_t b2 = __float_as_uint(v.z), b3 = __float_as_uint(v.w);
    hi01 = __byte_perm(b0, b1, 0x7632);
    hi23 = __byte_perm(b2, b3, 0x7632);
    float l0 = v.x - __uint_as_float(b0 & 0xffff0000u);
    float l1 = v.y - __uint_as_float(b1 & 0xffff0000u);
    float l2 = v.z - __uint_as_float(b2 & 0xffff0000u);
    float l3 = v.w - __uint_as_float(b3 & 0xffff0000u);
    __nv_bfloat162 p01 = __floats2bfloat162_rn(l0, l1);
    __nv_bfloat162 p23 = __floats2bfloat162_rn(l2, l3);
    lo01 = *reinterpret_cast<uint32_t*>(&p01);
    lo23 = *reinterpret_cast<uint32_t*>(&p23);
}

// ---------------- K0: CSR row pointers ----------------------------------------
__global__ void k_rowptr(const int* __restrict__ row, int n, int e) {
    int i = blockIdx.x * blockDim.x + threadIdx.x;
    if (i > n) return;
    int lo = 0, hi = e;
    while (lo < hi) { int mid = (lo + hi) >> 1; if (row[mid] < i) lo = mid + 1; else hi = mid; }
    g_rowptr[i] = lo;
}

// ---------------- K1: per-node attention logits -------------------------------
__global__ void k_nodelogits(const float* __restrict__ x, const float* __restrict__ a1w,
                             const float* __restrict__ a2w, int n) {
    __shared__ float sw[8 * 128];
    int tid = threadIdx.x;
    for (int i = tid; i < 512; i += 256) { sw[i] = a1w[i]; sw[512 + i] = a2w[i]; }
    __syncthreads();
    int warp = tid >> 5, lane = tid & 31;
    int nd = blockIdx.x * 8 + warp;
    if (nd >= n) return;
    float4 xv = *(const float4*)(x + (size_t)nd * 128 + lane * 4);
#pragma unroll
    for (int k = 0; k < 8; k++) {
        float4 wv = *(const float4*)(sw + k * 128 + lane * 4);
        float p = xv.x * wv.x + xv.y * wv.y + xv.z * wv.z + xv.w * wv.w;
        p += __shfl_xor_sync(0xffffffffu, p, 16);
        p += __shfl_xor_sync(0xffffffffu, p, 8);
        p += __shfl_xor_sync(0xffffffffu, p, 4);
        p += __shfl_xor_sync(0xffffffffu, p, 2);
        p += __shfl_xor_sync(0xffffffffu, p, 1);
        if (lane == 0) g_attn12[(size_t)nd * 8 + k] = p;
    }
}

// ---------------- K_pre: pre-split w1/w2 to bf16 hi/lo; zero stats ------------
__global__ void k_pre(const float* __restrict__ w1, const float* __restrict__ w2) {
    int h = blockIdx.x, tid = threadIdx.x;   // 4 blocks x 256
    for (int i = tid; i < OUT_H * 68; i += 256) {
        int o = i / 68, f = (i - o * 68) * 4;
        float4 v = *(const float4*)(w1 + ((size_t)h * OUT_H + o) * F_MLP + f);
        uint32_t h01, h23, l01, l23;
        split4(v, h01, h23, l01, l23);
        *(uint2*)(g_w1s + ((size_t)(h * 2 + 0) * OUT_H + o) * F_MLP + f) = make_uint2(h01, h23);
        *(uint2*)(g_w1s + ((size_t)(h * 2 + 1) * OUT_H + o) * F_MLP + f) = make_uint2(l01, l23);
    }
    for (int i = tid; i < OUT_H * 16; i += 256) {
        int p = i >> 4, f = (i & 15) * 4;
        float4 v = *(const float4*)(w2 + (size_t)h * 4096 + p * 64 + f);
        uint32_t h01, h23, l01, l23;
        split4(v, h01, h23, l01, l23);
        *(uint2*)(g_w2s + ((size_t)(h * 2 + 0) * OUT_H + p) * 64 + f) = make_uint2(h01, h23);
        *(uint2*)(g_w2s + ((size_t)(h * 2 + 1) * OUT_H + p) * 64 + f) = make_uint2(l01, l23);
    }
    if (h == 0) { g_sum[tid] = 0.f; g_sqsum[tid] = 0.f; }
}

// ---------------- K_xsplit: pre-split x ---------------------------------------
__global__ void k_xsplit(const float* __restrict__ x, int n) {
    size_t i = (size_t)blockIdx.x * blockDim.x + threadIdx.x;
    if (i * 4 >= (size_t)n * 128) return;
    float4 v = *(const float4*)(x + i * 4);
    uint32_t h01, h23, l01, l23;
    split4(v, h01, h23, l01, l23);
    *(uint2*)(g_xhi + i * 4) = make_uint2(h01, h23);
    *(uint2*)(g_xlo + i * 4) = make_uint2(l01, l23);
}

// ---------------- K2: edge softmax + aggregation (warp per node) --------------
__device__ __forceinline__ void edge_logits(const float* __restrict__ ea,
                                            const float* s_aew, int e2, int ci,
                                            const float* a1h, float* lg) {
    const float4* ep = (const float4*)(ea + (size_t)e2 * 16);
    float4 q0 = ep[0], q1 = ep[1], q2 = ep[2], q3 = ep[3];
    float4 a2v = *(const float4*)(g_attn12 + (size_t)ci * 8 + 4);
    float a2a[4] = {a2v.x, a2v.y, a2v.z, a2v.w};
#pragma unroll
    for (int h = 0; h < 4; h++) {
        const float* wq = s_aew + h * 16;
        float d = q0.x * wq[0] + q0.y * wq[1] + q0.z * wq[2] + q0.w * wq[3]
                + q1.x * wq[4] + q1.y * wq[5] + q1.z * wq[6] + q1.w * wq[7]
                + q2.x * wq[8] + q2.y * wq[9] + q2.z * wq[10] + q2.w * wq[11]
                + q3.x * wq[12] + q3.y * wq[13] + q3.z * wq[14] + q3.w * wq[15];
        lg[h] = (a1h[h] + a2a[h] + d) * 0.125f;
    }
}

__global__ void __launch_bounds__(256, 2) k_edge(const float* __restrict__ x,
                                                 const int* __restrict__ col,
                                                 const float* __restrict__ ea,
                                                 const float* __restrict__ aew, int n) {
    __shared__ float s_aew[64];
    __shared__ float s_w[8 * 32 * 4];
    __shared__ int   s_c[8 * 32];
    int tid = threadIdx.x;
    if (tid < 64) s_aew[tid] = aew[tid];
    __syncthreads();
    int warp = tid >> 5, lane = tid & 31;
    int nd = blockIdx.x * 8 + warp;
    if (nd >= n) return;
    int start = g_rowptr[nd], end = g_rowptr[nd + 1];
    int deg = end - start;
    float a1h[4];
    {
        float4 a1v = *(const float4*)(g_attn12 + (size_t)nd * 8);
        a1h[0] = a1v.x; a1h[1] = a1v.y; a1h[2] = a1v.z; a1h[3] = a1v.w;
    }
    float* swp = s_w + warp * 128;
    int*   scp = s_c + warp * 32;

    float m[4], inv[4];

    if (deg <= 32) {
        int e2 = start + lane;
        bool have = (e2 < end);
        float lg[4] = {-CUDART_INF_F, -CUDART_INF_F, -CUDART_INF_F, -CUDART_INF_F};
        int ci = 0;
        if (have) { ci = col[e2]; edge_logits(ea, s_aew, e2, ci, a1h, lg); }
#pragma unroll
        for (int h = 0; h < 4; h++) {
            float mm = lg[h];
#pragma unroll
            for (int off = 16; off >= 1; off >>= 1)
                mm = fmaxf(mm, __shfl_xor_sync(0xffffffffu, mm, off));
            float ex = have ? __expf(lg[h] - mm) : 0.f;
            float ssum = ex;
#pragma unroll
            for (int off = 16; off >= 1; off >>= 1)
                ssum += __shfl_xor_sync(0xffffffffu, ssum, off);
            float iv = 1.f / (ssum + 1e-16f);
            swp[lane * 4 + h] = ex * iv;
        }
        scp[lane] = ci;
        m[0] = 0.f;
    } else {
        float mm[4] = {-CUDART_INF_F, -CUDART_INF_F, -CUDART_INF_F, -CUDART_INF_F};
        float s[4] = {0.f, 0.f, 0.f, 0.f};
        for (int base = start; base < end; base += 32) {
            int e2 = base + lane;
            if (e2 < end) {
                int ci = col[e2];
                float lg[4];
                edge_logits(ea, s_aew, e2, ci, a1h, lg);
                *(float4*)(g_lg + (size_t)e2 * 4) = make_float4(lg[0], lg[1], lg[2], lg[3]);
#pragma unroll
                for (int h = 0; h < 4; h++) {
                    if (lg[h] > mm[h]) { s[h] = s[h] * __expf(mm[h] - lg[h]) + 1.f; mm[h] = lg[h]; }
                    else               { s[h] += __expf(lg[h] - mm[h]); }
                }
            }
        }
#pragma unroll
        for (int off = 16; off >= 1; off >>= 1) {
#pragma unroll
            for (int h = 0; h < 4; h++) {
                float om = __shfl_xor_sync(0xffffffffu, mm[h], off);
                float os = __shfl_xor_sync(0xffffffffu, s[h], off);
                float nm = fmaxf(mm[h], om);
                float t = (s[h] > 0.f ? s[h] * __expf(mm[h] - nm) : 0.f)
                        + (os > 0.f ? os * __expf(om - nm) : 0.f);
                mm[h] = nm; s[h] = t;
            }
        }
#pragma unroll
        for (int h = 0; h < 4; h++) { m[h] = mm[h]; inv[h] = 1.f / (s[h] + 1e-16f); }
    }

    float4 acc[4];
#pragma unroll
    for (int h = 0; h < 4; h++) acc[h] = make_float4(0.f, 0.f, 0.f, 0.f);
    float acce[4] = {0.f, 0.f, 0.f, 0.f};

    for (int base = start; base < end; base += 32) {
        int cnt = min(32, end - base);
        if (deg > 32) {
            int e2 = base + lane;
            __syncwarp();
            if (e2 < end) {
                float4 lgv = *(const float4*)(g_lg + (size_t)e2 * 4);
                swp[lane * 4 + 0] = __expf(lgv.x - m[0]) * inv[0];
                swp[lane * 4 + 1] = __expf(lgv.y - m[1]) * inv[1];
                swp[lane * 4 + 2] = __expf(lgv.z - m[2]) * inv[2];
                swp[lane * 4 + 3] = __expf(lgv.w - m[3]) * inv[3];
                scp[lane] = col[e2];
            }
        }
        __syncwarp();
#pragma unroll 8
        for (int j = 0; j < cnt; j++) {
            int cj = scp[j];
            float4 wv = *(const float4*)(swp + j * 4);
            float4 xv = *(const float4*)(x + (size_t)cj * 128 + lane * 4);
            acc[0].x += wv.x * xv.x; acc[0].y += wv.x * xv.y; acc[0].z += wv.x * xv.z; acc[0].w += wv.x * xv.w;
            acc[1].x += wv.y * xv.x; acc[1].y += wv.y * xv.y; acc[1].z += wv.y * xv.z; acc[1].w += wv.y * xv.w;
            acc[2].x += wv.z * xv.x; acc[2].y += wv.z * xv.y; acc[2].z += wv.z * xv.z; acc[2].w += wv.z * xv.w;
            acc[3].x += wv.w * xv.x; acc[3].y += wv.w * xv.y; acc[3].z += wv.w * xv.z; acc[3].w += wv.w * xv.w;
            if (lane < 16) {
                float eav = ea[(size_t)(base + j) * 16 + lane];
                acce[0] += wv.x * eav; acce[1] += wv.y * eav;
                acce[2] += wv.z * eav; acce[3] += wv.w * eav;
            }
        }
    }
    // epilogue: write xobj / xe as bf16 hi/lo
#pragma unroll
    for (int h = 0; h < 4; h++) {
        uint32_t h01, h23, l01, l23;
        split4(acc[h], h01, h23, l01, l23);
        size_t off = ((size_t)nd * 4 + h) * 128 + lane * 4;
        *(uint2*)(g_obhi + off) = make_uint2(h01, h23);
        *(uint2*)(g_oblo + off) = make_uint2(l01, l23);
    }
    if (lane < 16) {
#pragma unroll
        for (int h = 0; h < 4; h++) {
            float v = acce[h];
            uint32_t b = __float_as_uint(v);
            size_t off = ((size_t)nd * 4 + h) * 16 + lane;
            g_xehi[off] = __ushort_as_bfloat16((unsigned short)(b >> 16));
            g_xelo[off] = __float2bfloat16(v - __uint_as_float(b & 0xffff0000u));
        }
    }
}

// ---------------- K3: MLP layer 1 via mma.sync, streamed buffers --------------
// smem: A[128][280] bf16 (71680 B) + B[64][280] bf16 (35840 B) = 107520 -> 2 CTA/SM
#define SA1 280
#define SMB1 71680
#define MLP1_SMEM 107520
__global__ void __launch_bounds__(256, 2) k_mlp1h(const float* __restrict__ b1, int n) {
    extern __shared__ char smem[];
    uint32_t sb = smem_u32(smem);
    int tid = threadIdx.x, lane = tid & 31, wid = tid >> 5;
    int h = blockIdx.y;
    int n0 = blockIdx.x * 128;

    float c4[2][4][4] = {};
    int wm = wid & 3, wn = wid >> 2;
    uint32_t aB = sb + wm * 32 * (SA1 * 2);
    uint32_t bB = sb + SMB1 + wn * 32 * (SA1 * 2);

    // ---- fill A (hi) + B (hi) ----
    {
        for (int i = tid; i < 128 * 34; i += 256) {
            int r = i / 34, c = i - r * 34;
            int nd = n0 + r;
            uint32_t dst = sb + r * 560 + c * 16;
            if (nd < n) {
                const char* src;
                if (c < 16)      src = (const char*)(g_xhi + (size_t)nd * 128) + c * 16;
                else if (c < 32) src = (const char*)(g_obhi + ((size_t)nd * 4 + h) * 128) + (c - 16) * 16;
                else             src = (const char*)(g_xehi + ((size_t)nd * 4 + h) * 16) + (c - 32) * 16;
                cpa16(dst, src);
            } else {
                *(uint4*)(smem + r * 560 + c * 16) = make_uint4(0, 0, 0, 0);
            }
        }
        const __nv_bfloat16* ws = g_w1s + (size_t)(h * 2 + 0) * OUT_H * F_MLP;
        for (int i = tid; i < 64 * 34; i += 256) {
            int r = i / 34, c = i - r * 34;
            cpa16(sb + SMB1 + r * 560 + c * 16, (const char*)(ws + (size_t)r * F_MLP) + c * 16);
        }
        CPWAIT();
        __syncthreads();
    }
    mma_block<17, SA1, SA1>(c4, aB, bB, lane);      // A_hi * B_hi
    __syncthreads();
    // ---- refill B (lo) ----
    {
        const __nv_bfloat16* ws = g_w1s + (size_t)(h * 2 + 1) * OUT_H * F_MLP;
        for (int i = tid; i < 64 * 34; i += 256) {
            int r = i / 34, c = i - r * 34;
            cpa16(sb + SMB1 + r * 560 + c * 16, (const char*)(ws + (size_t)r * F_MLP) + c * 16);
        }
        CPWAIT();
        __syncthreads();
    }
    mma_block<17, SA1, SA1>(c4, aB, bB, lane);      // A_hi * B_lo
    __syncthreads();
    // ---- refill A (lo) + B (hi) ----
    {
        for (int i = tid; i < 128 * 34; i += 256) {
            int r = i / 34, c = i - r * 34;
            int nd = n0 + r;
            uint32_t dst = sb + r * 560 + c * 16;
            if (nd < n) {
                const char* src;
                if (c < 16)      src = (const char*)(g_xlo + (size_t)nd * 128) + c * 16;
                else if (c < 32) src = (const char*)(g_oblo + ((size_t)nd * 4 + h) * 128) + (c - 16) * 16;
                else             src = (const char*)(g_xelo + ((size_t)nd * 4 + h) * 16) + (c - 32) * 16;
                cpa16(dst, src);
            } else {
                *(uint4*)(smem + r * 560 + c * 16) = make_uint4(0, 0, 0, 0);
            }
        }
        const __nv_bfloat16* ws = g_w1s + (size_t)(h * 2 + 0) * OUT_H * F_MLP;
        for (int i = tid; i < 64 * 34; i += 256) {
            int r = i / 34, c = i - r * 34;
            cpa16(sb + SMB1 + r * 560 + c * 16, (const char*)(ws + (size_t)r * F_MLP) + c * 16);
        }
        CPWAIT();
        __syncthreads();
    }
    mma_block<17, SA1, SA1>(c4, aB, bB, lane);      // A_lo * B_hi

    // epilogue: bias + ReLU -> g_h1
    const float* bb = b1 + h * 64;
    int g = lane >> 2, tc2 = 2 * (lane & 3);
#pragma unroll
    for (int mi = 0; mi < 2; mi++) {
#pragma unroll
        for (int ni = 0; ni < 4; ni++) {
            int colo = wn * 32 + ni * 8 + tc2;
            float2 bv = *(const float2*)(bb + colo);
            int ndr = n0 + wm * 32 + mi * 16 + g;
            float* dst = g_h1 + (size_t)ndr * 256 + h * 64 + colo;
            if (ndr < n) {
                *(float2*)dst = make_float2(fmaxf(c4[mi][ni][0] + bv.x, 0.f),
                                            fmaxf(c4[mi][ni][1] + bv.y, 0.f));
            }
            if (ndr + 8 < n) {
                *(float2*)(dst + 8 * 256) = make_float2(fmaxf(c4[mi][ni][2] + bv.x, 0.f),
                                                        fmaxf(c4[mi][ni][3] + bv.y, 0.f));
            }
        }
    }
}

// ---------------- K3b: BN partial sums over g_h1 ------------------------------
__global__ void k_bnsum(int n) {
    int t = threadIdx.x;   // 256 -> (h,o)
    float s = 0.f, q = 0.f;
    for (int nd = blockIdx.x; nd < n; nd += gridDim.x) {
        float v = g_h1[(size_t)nd * 256 + t];
        s += v; q += v * v;
    }
    atomicAdd(&g_sum[t], s);
    atomicAdd(&g_sqsum[t], q);
}

// ---------------- K4: finalize BN stats ---------------------------------------
__global__ void k_stats(const float* __restrict__ gamma, const float* __restrict__ beta, int n) {
    int i = threadIdx.x;   // 256
    float inv_n = 1.f / (float)n;
    float mu = g_sum[i] * inv_n;
    float var = g_sqsum[i] * inv_n - mu * mu;
    float r = rsqrtf(var + 1e-5f);
    float a = r * gamma[i];
    g_a[i] = a;
    g_c[i] = beta[i] - mu * a;
}

// ---------------- K5: BN apply + MLP layer 2 via mma.sync ---------------------
#define SA2 72
#define A2HI 0
#define A2LO (128 * SA2 * 2)                 // 18432
#define B2HI (2 * 128 * SA2 * 2)             // 36864
#define B2LO (B2HI + 64 * SA2 * 2)           // 46080
#define MLP2_SMEM (B2LO + 64 * SA2 * 2)      // 55296
__global__ void __launch_bounds__(256) k_mlp2h(const float* __restrict__ b2,
                                               float* __restrict__ out, int n) {
    extern __shared__ char smem[];
    uint32_t sb = smem_u32(smem);
    int tid = threadIdx.x, lane = tid & 31, wid = tid >> 5;
    int h = blockIdx.y;
    int n0 = blockIdx.x * 128;

    // fill B hi/lo via cp.async from pre-split w2
    {
        const char* wh = (const char*)(g_w2s + (size_t)(h * 2 + 0) * OUT_H * 64);
        const char* wl = (const char*)(g_w2s + (size_t)(h * 2 + 1) * OUT_H * 64);
        for (int i = tid; i < 64 * 8; i += 256) {
            int r = i >> 3, c = i & 7;
            cpa16(sb + B2HI + r * 144 + c * 16, wh + (size_t)r * 128 + c * 16);
            cpa16(sb + B2LO + r * 144 + c * 16, wl + (size_t)r * 128 + c * 16);
        }
    }
    // fill A: BN-applied h1 (inline split; K=64 only)
    for (int i = tid; i < 128 * 16; i += 256) {
        int nl = i >> 4, f = (i & 15) * 4;
        int nd = n0 + nl;
        float4 v = make_float4(0.f, 0.f, 0.f, 0.f);
        if (nd < n) {
            float4 hv = *(const float4*)(g_h1 + (size_t)nd * 256 + h * 64 + f);
            float4 av = *(const float4*)(g_a + h * 64 + f);
            float4 cv = *(const float4*)(g_c + h * 64 + f);
            v = make_float4(hv.x * av.x + cv.x, hv.y * av.y + cv.y,
                            hv.z * av.z + cv.z, hv.w * av.w + cv.w);
        }
        uint32_t h01, h23, l01, l23;
        split4(v, h01, h23, l01, l23);
        *(uint2*)(smem + A2HI + (nl * SA2 + f) * 2) = make_uint2(h01, h23);
        *(uint2*)(smem + A2LO + (nl * SA2 + f) * 2) = make_uint2(l01, l23);
    }
    CPWAIT();
    __syncthreads();

    float c4[2][4][4] = {};
    int wm = wid & 3, wn = wid >> 2;
    uint32_t aH = sb + A2HI + wm * 32 * SA2 * 2;
    uint32_t aL = sb + A2LO + wm * 32 * SA2 * 2;
    uint32_t bH = sb + B2HI + wn * 32 * SA2 * 2;
    uint32_t bL = sb + B2LO + wn * 32 * SA2 * 2;
    mma_block<4, SA2, SA2>(c4, aH, bH, lane);
    mma_block<4, SA2, SA2>(c4, aH, bL, lane);
    mma_block<4, SA2, SA2>(c4, aL, bH, lane);

    // epilogue: bias -> out
    const float* bb = b2 + h * 64;
    int g = lane >> 2, tc2 = 2 * (lane & 3);
#pragma unroll
    for (int mi = 0; mi < 2; mi++) {
#pragma unroll
        for (int ni = 0; ni < 4; ni++) {
            int colo = wn * 32 + ni * 8 + tc2;
            float2 bv = *(const float2*)(bb + colo);
            int ndr = n0 + wm * 32 + mi * 16 + g;
            float* dst = out + (size_t)ndr * 256 + h * 64 + colo;
            if (ndr < n)
                *(float2*)dst = make_float2(c4[mi][ni][0] + bv.x, c4[mi][ni][1] + bv.y);
            if (ndr + 8 < n)
                *(float2*)(dst + 8 * 256) =
                    make_float2(c4[mi][ni][2] + bv.x, c4[mi][ni][3] + bv.y);
        }
    }
}

// ---------------- launch ------------------------------------------------------
extern "C" void kernel_launch(void* const* d_in, const int* in_sizes, int n_in,
                              void* d_out, int out_size) {
    const float* x     = (const float*)d_in[0];
    const int*   row   = (const int*)d_in[1];
    const int*   col   = (const int*)d_in[2];
    const float* ea    = (const float*)d_in[3];
    const float* a1w   = (const float*)d_in[4];
    const float* a2w   = (const float*)d_in[5];
    const float* aew   = (const float*)d_in[6];
    const float* w1    = (const float*)d_in[7];
    const float* b1    = (const float*)d_in[8];
    const float* gamma = (const float*)d_in[9];
    const float* beta  = (const float*)d_in[10];
    const float* w2    = (const float*)d_in[11];
    const float* b2    = (const float*)d_in[12];
    float* out = (float*)d_out;

    int n = in_sizes[0] / IN_DIM;
    int e = in_sizes[1];

    cudaFuncSetAttribute(k_mlp1h, cudaFuncAttributeMaxDynamicSharedMemorySize, MLP1_SMEM);
    cudaFuncSetAttribute(k_mlp2h, cudaFuncAttributeMaxDynamicSharedMemorySize, MLP2_SMEM);

    k_rowptr<<<(n + 256) / 256, 256>>>(row, n, e);
    k_nodelogits<<<(n + 7) / 8, 256>>>(x, a1w, a2w, n);
    k_pre<<<4, 256>>>(w1, w2);
    k_xsplit<<<(n * 32 + 255) / 256, 256>>>(x, n);
    k_edge<<<(n + 7) / 8, 256>>>(x, col, ea, aew, n);
    dim3 g3((n + 127) / 128, 4);
    k_mlp1h<<<g3, 256, MLP1_SMEM>>>(b1, n);
    k_bnsum<<<296, 256>>>(n);
    k_stats<<<1, 256>>>(gamma, beta, n);
    k_mlp2h<<<g3, 256, MLP2_SMEM>>>(b2, out, n);
}

// round 14
// speedup vs baseline: 1.3340x; 1.1317x over previous
#include <cuda_runtime.h>
#include <cuda_bf16.h>
#include <math_constants.h>
#include <cstdint>

#define MAXN 100000
#define MAXE 1600000
#define IN_DIM 128
#define EDGE_DIM 16
#define NH 4
#define OUT_H 64
#define F_MLP 272   // 2*128+16

// ---------------- device scratch ----------------------------------------------
__device__ int   g_rowptr[MAXN + 1];
__device__ float g_attn12[(size_t)MAXN * 8];
__device__ float g_lg[(size_t)MAXE * 4];               // logits then final weights
__device__ float g_h1[(size_t)MAXN * NH * OUT_H];      // [n][h][64] = [n][256]
__device__ float g_sum[NH * OUT_H];
__device__ float g_sqsum[NH * OUT_H];
__device__ float g_a[NH * OUT_H];
__device__ float g_c[NH * OUT_H];
// bf16 hi/lo pre-split data
__device__ __nv_bfloat16 g_xhi[(size_t)MAXN * 128];
__device__ __nv_bfloat16 g_xlo[(size_t)MAXN * 128];
__device__ __nv_bfloat16 g_obhi[(size_t)MAXN * NH * 128];
__device__ __nv_bfloat16 g_oblo[(size_t)MAXN * NH * 128];
__device__ __nv_bfloat16 g_xehi[(size_t)MAXN * NH * 16];
__device__ __nv_bfloat16 g_xelo[(size_t)MAXN * NH * 16];
__device__ __nv_bfloat16 g_w1s[(size_t)NH * 2 * OUT_H * F_MLP];  // [h][pass][o][272]
__device__ __nv_bfloat16 g_w2s[(size_t)NH * 2 * OUT_H * OUT_H];  // [h][pass][p][64]

// ---------------- helpers ------------------------------------------------------
__device__ __forceinline__ uint32_t smem_u32(const void* p) {
    uint32_t a;
    asm("{ .reg .u64 t; cvta.to.shared.u64 t, %1; cvt.u32.u64 %0, t; }" : "=r"(a) : "l"(p));
    return a;
}
__device__ __forceinline__ void cpa16(uint32_t dst, const void* src) {
    asm volatile("cp.async.cg.shared.global [%0], [%1], 16;" :: "r"(dst), "l"(src));
}
#define CPWAIT() asm volatile("cp.async.commit_group;\n\tcp.async.wait_group 0;" ::: "memory")

__device__ __forceinline__ void ldsm4(uint32_t* r, uint32_t a) {
    asm volatile("ldmatrix.sync.aligned.m8n8.x4.shared.b16 {%0,%1,%2,%3}, [%4];"
        : "=r"(r[0]), "=r"(r[1]), "=r"(r[2]), "=r"(r[3]) : "r"(a));
}
__device__ __forceinline__ void ldsm2(uint32_t* r, uint32_t a) {
    asm volatile("ldmatrix.sync.aligned.m8n8.x2.shared.b16 {%0,%1}, [%2];"
        : "=r"(r[0]), "=r"(r[1]) : "r"(a));
}
__device__ __forceinline__ void mma_bf16(float* c, const uint32_t* a,
                                         uint32_t b0, uint32_t b1) {
    asm volatile("mma.sync.aligned.m16n8k16.row.col.f32.bf16.bf16.f32 "
        "{%0,%1,%2,%3}, {%4,%5,%6,%7}, {%8,%9}, {%0,%1,%2,%3};"
        : "+f"(c[0]), "+f"(c[1]), "+f"(c[2]), "+f"(c[3])
        : "r"(a[0]), "r"(a[1]), "r"(a[2]), "r"(a[3]), "r"(b0), "r"(b1));
}

template<int KSTEPS, int SA, int SB>
__device__ __forceinline__ void mma_block(float c[2][4][4], uint32_t aBase,
                                          uint32_t bBase, int lane) {
    uint32_t aRow = aBase + (uint32_t)(((lane & 15) * SA + ((lane >> 4) << 3)) * 2);
    uint32_t bRow = bBase + (uint32_t)(((lane & 7) * SB + (((lane >> 3) & 1) << 3)) * 2);
#pragma unroll
    for (int ks = 0; ks < KSTEPS; ks++) {
        uint32_t a0[4], a1[4];
        ldsm4(a0, aRow + ks * 32);
        ldsm4(a1, aRow + 16 * SA * 2 + ks * 32);
#pragma unroll
        for (int ni = 0; ni < 4; ni++) {
            uint32_t b[2];
            ldsm2(b, bRow + ni * 8 * SB * 2 + ks * 32);
            mma_bf16(c[0][ni], a0, b[0], b[1]);
            mma_bf16(c[1][ni], a1, b[0], b[1]);
        }
    }
}

// split fp32 float4 -> bf16 hi pair-words + lo pair-words
__device__ __forceinline__ void split4(float4 v, uint32_t& hi01, uint32_t& hi23,
                                       uint32_t& lo01, uint32_t& lo23) {
    uint32_t b0 = __float_as_uint(v.x), b1 = __float_as_uint(v.y);
    uint32_t b2 = __float_as_uint(v.z), b3 = __float_as_uint(v.w);
    hi01 = __byte_perm(b0, b1, 0x7632);
    hi23 = __byte_perm(b2, b3, 0x7632);
    float l0 = v.x - __uint_as_float(b0 & 0xffff0000u);
    float l1 = v.y - __uint_as_float(b1 & 0xffff0000u);
    float l2 = v.z - __uint_as_float(b2 & 0xffff0000u);
    float l3 = v.w - __uint_as_float(b3 & 0xffff0000u);
    __nv_bfloat162 p01 = __floats2bfloat162_rn(l0, l1);
    __nv_bfloat162 p23 = __floats2bfloat162_rn(l2, l3);
    lo01 = *reinterpret_cast<uint32_t*>(&p01);
    lo23 = *reinterpret_cast<uint32_t*>(&p23);
}

// ---------------- K0: CSR row pointers ----------------------------------------
__global__ void k_rowptr(const int* __restrict__ row, int n, int e) {
    int i = blockIdx.x * blockDim.x + threadIdx.x;
    if (i > n) return;
    int lo = 0, hi = e;
    while (lo < hi) { int mid = (lo + hi) >> 1; if (row[mid] < i) lo = mid + 1; else hi = mid; }
    g_rowptr[i] = lo;
}

// ---------------- K1: per-node attention logits + x hi/lo split ---------------
__global__ void k_nodelogits(const float* __restrict__ x, const float* __restrict__ a1w,
                             const float* __restrict__ a2w, int n) {
    __shared__ float sw[8 * 128];
    int tid = threadIdx.x;
    for (int i = tid; i < 512; i += 256) { sw[i] = a1w[i]; sw[512 + i] = a2w[i]; }
    __syncthreads();
    int warp = tid >> 5, lane = tid & 31;
    int nd = blockIdx.x * 8 + warp;
    if (nd >= n) return;
    float4 xv = *(const float4*)(x + (size_t)nd * 128 + lane * 4);
    // fused x split
    {
        uint32_t h01, h23, l01, l23;
        split4(xv, h01, h23, l01, l23);
        *(uint2*)(g_xhi + (size_t)nd * 128 + lane * 4) = make_uint2(h01, h23);
        *(uint2*)(g_xlo + (size_t)nd * 128 + lane * 4) = make_uint2(l01, l23);
    }
#pragma unroll
    for (int k = 0; k < 8; k++) {
        float4 wv = *(const float4*)(sw + k * 128 + lane * 4);
        float p = xv.x * wv.x + xv.y * wv.y + xv.z * wv.z + xv.w * wv.w;
        p += __shfl_xor_sync(0xffffffffu, p, 16);
        p += __shfl_xor_sync(0xffffffffu, p, 8);
        p += __shfl_xor_sync(0xffffffffu, p, 4);
        p += __shfl_xor_sync(0xffffffffu, p, 2);
        p += __shfl_xor_sync(0xffffffffu, p, 1);
        if (lane == 0) g_attn12[(size_t)nd * 8 + k] = p;
    }
}

// ---------------- K_pre: pre-split w1/w2 to bf16 hi/lo; zero stats ------------
__global__ void k_pre(const float* __restrict__ w1, const float* __restrict__ w2) {
    int h = blockIdx.x, tid = threadIdx.x;   // 4 blocks x 256
    for (int i = tid; i < OUT_H * 68; i += 256) {
        int o = i / 68, f = (i - o * 68) * 4;
        float4 v = *(const float4*)(w1 + ((size_t)h * OUT_H + o) * F_MLP + f);
        uint32_t h01, h23, l01, l23;
        split4(v, h01, h23, l01, l23);
        *(uint2*)(g_w1s + ((size_t)(h * 2 + 0) * OUT_H + o) * F_MLP + f) = make_uint2(h01, h23);
        *(uint2*)(g_w1s + ((size_t)(h * 2 + 1) * OUT_H + o) * F_MLP + f) = make_uint2(l01, l23);
    }
    for (int i = tid; i < OUT_H * 16; i += 256) {
        int p = i >> 4, f = (i & 15) * 4;
        float4 v = *(const float4*)(w2 + (size_t)h * 4096 + p * 64 + f);
        uint32_t h01, h23, l01, l23;
        split4(v, h01, h23, l01, l23);
        *(uint2*)(g_w2s + ((size_t)(h * 2 + 0) * OUT_H + p) * 64 + f) = make_uint2(h01, h23);
        *(uint2*)(g_w2s + ((size_t)(h * 2 + 1) * OUT_H + p) * 64 + f) = make_uint2(l01, l23);
    }
    if (h == 0) { g_sum[tid] = 0.f; g_sqsum[tid] = 0.f; }
}

// ---------------- K2a: attention softmax + edge-feature aggregation -----------
__device__ __forceinline__ void logits_from_q(float4 q0, float4 q1, float4 q2, float4 q3,
                                              const float* s_aew, int ci,
                                              const float* a1h, float* lg) {
    float4 a2v = *(const float4*)(g_attn12 + (size_t)ci * 8 + 4);
    float a2a[4] = {a2v.x, a2v.y, a2v.z, a2v.w};
#pragma unroll
    for (int h = 0; h < 4; h++) {
        const float* wq = s_aew + h * 16;
        float d = q0.x * wq[0] + q0.y * wq[1] + q0.z * wq[2] + q0.w * wq[3]
                + q1.x * wq[4] + q1.y * wq[5] + q1.z * wq[6] + q1.w * wq[7]
                + q2.x * wq[8] + q2.y * wq[9] + q2.z * wq[10] + q2.w * wq[11]
                + q3.x * wq[12] + q3.y * wq[13] + q3.z * wq[14] + q3.w * wq[15];
        lg[h] = (a1h[h] + a2a[h] + d) * 0.125f;
    }
}

__global__ void __launch_bounds__(256) k_attn(const int* __restrict__ col,
                                              const float* __restrict__ ea,
                                              const float* __restrict__ aew, int n) {
    __shared__ float s_aew[64];
    __shared__ float s_ea[8 * 32 * 16];   // [warp][edge][16] 16KB
    __shared__ float s_w[8 * 128];        // [warp][edge][4]
    int tid = threadIdx.x;
    if (tid < 64) s_aew[tid] = aew[tid];
    __syncthreads();
    int warp = tid >> 5, lane = tid & 31;
    int nd = blockIdx.x * 8 + warp;
    if (nd >= n) return;
    int start = g_rowptr[nd], end = g_rowptr[nd + 1];
    int deg = end - start;
    float a1h[4];
    {
        float4 a1v = *(const float4*)(g_attn12 + (size_t)nd * 8);
        a1h[0] = a1v.x; a1h[1] = a1v.y; a1h[2] = a1v.z; a1h[3] = a1v.w;
    }
    float* eap = s_ea + warp * 512;
    float* swp = s_w + warp * 128;
    float acce[4] = {0.f, 0.f, 0.f, 0.f};

    if (deg <= 32) {
        int e2 = start + lane;
        bool have = (e2 < end);
        float lg[4] = {-CUDART_INF_F, -CUDART_INF_F, -CUDART_INF_F, -CUDART_INF_F};
        if (have) {
            int ci = col[e2];
            const float4* ep = (const float4*)(ea + (size_t)e2 * 16);
            float4 q0 = ep[0], q1 = ep[1], q2 = ep[2], q3 = ep[3];
            *(float4*)(eap + lane * 16 + 0)  = q0;
            *(float4*)(eap + lane * 16 + 4)  = q1;
            *(float4*)(eap + lane * 16 + 8)  = q2;
            *(float4*)(eap + lane * 16 + 12) = q3;
            logits_from_q(q0, q1, q2, q3, s_aew, ci, a1h, lg);
        }
        float w[4];
#pragma unroll
        for (int h = 0; h < 4; h++) {
            float mm = lg[h];
#pragma unroll
            for (int off = 16; off >= 1; off >>= 1)
                mm = fmaxf(mm, __shfl_xor_sync(0xffffffffu, mm, off));
            float ex = have ? __expf(lg[h] - mm) : 0.f;
            float ssum = ex;
#pragma unroll
            for (int off = 16; off >= 1; off >>= 1)
                ssum += __shfl_xor_sync(0xffffffffu, ssum, off);
            w[h] = ex / (ssum + 1e-16f);
        }
        if (have) {
            *(float4*)(swp + lane * 4) = make_float4(w[0], w[1], w[2], w[3]);
            *(float4*)(g_lg + (size_t)e2 * 4) = make_float4(w[0], w[1], w[2], w[3]);
        }
        __syncwarp();
        if (lane < 16) {
            for (int j = 0; j < deg; j++) {
                float4 wv = *(const float4*)(swp + j * 4);
                float eav = eap[j * 16 + lane];
                acce[0] += wv.x * eav; acce[1] += wv.y * eav;
                acce[2] += wv.z * eav; acce[3] += wv.w * eav;
            }
        }
    } else {
        // general path (rare): logits -> g_lg, online softmax
        float mm[4] = {-CUDART_INF_F, -CUDART_INF_F, -CUDART_INF_F, -CUDART_INF_F};
        float s[4] = {0.f, 0.f, 0.f, 0.f};
        for (int base = start; base < end; base += 32) {
            int e2 = base + lane;
            if (e2 < end) {
                int ci = col[e2];
                const float4* ep = (const float4*)(ea + (size_t)e2 * 16);
                float lg[4];
                logits_from_q(ep[0], ep[1], ep[2], ep[3], s_aew, ci, a1h, lg);
                *(float4*)(g_lg + (size_t)e2 * 4) = make_float4(lg[0], lg[1], lg[2], lg[3]);
#pragma unroll
                for (int h = 0; h < 4; h++) {
                    if (lg[h] > mm[h]) { s[h] = s[h] * __expf(mm[h] - lg[h]) + 1.f; mm[h] = lg[h]; }
                    else               { s[h] += __expf(lg[h] - mm[h]); }
                }
            }
        }
#pragma unroll
        for (int off = 16; off >= 1; off >>= 1) {
#pragma unroll
            for (int h = 0; h < 4; h++) {
                float om = __shfl_xor_sync(0xffffffffu, mm[h], off);
                float os = __shfl_xor_sync(0xffffffffu, s[h], off);
                float nm = fmaxf(mm[h], om);
                float t = (s[h] > 0.f ? s[h] * __expf(mm[h] - nm) : 0.f)
                        + (os > 0.f ? os * __expf(om - nm) : 0.f);
                mm[h] = nm; s[h] = t;
            }
        }
        float inv[4];
#pragma unroll
        for (int h = 0; h < 4; h++) inv[h] = 1.f / (s[h] + 1e-16f);
        // second pass: normalize weights in g_lg + xe aggregation
        for (int base = start; base < end; base += 32) {
            int cnt = min(32, end - base);
            int e2 = base + lane;
            __syncwarp();
            if (e2 < end) {
                float4 lgv = *(const float4*)(g_lg + (size_t)e2 * 4);
                float4 wv = make_float4(__expf(lgv.x - mm[0]) * inv[0],
                                        __expf(lgv.y - mm[1]) * inv[1],
                                        __expf(lgv.z - mm[2]) * inv[2],
                                        __expf(lgv.w - mm[3]) * inv[3]);
                *(float4*)(g_lg + (size_t)e2 * 4) = wv;
                *(float4*)(swp + lane * 4) = wv;
                const float4* ep = (const float4*)(ea + (size_t)e2 * 16);
                *(float4*)(eap + lane * 16 + 0)  = ep[0];
                *(float4*)(eap + lane * 16 + 4)  = ep[1];
                *(float4*)(eap + lane * 16 + 8)  = ep[2];
                *(float4*)(eap + lane * 16 + 12) = ep[3];
            }
            __syncwarp();
            if (lane < 16) {
                for (int j = 0; j < cnt; j++) {
                    float4 wv = *(const float4*)(swp + j * 4);
                    float eav = eap[j * 16 + lane];
                    acce[0] += wv.x * eav; acce[1] += wv.y * eav;
                    acce[2] += wv.z * eav; acce[3] += wv.w * eav;
                }
            }
        }
    }
    if (lane < 16) {
#pragma unroll
        for (int h = 0; h < 4; h++) {
            float v = acce[h];
            uint32_t b = __float_as_uint(v);
            size_t off = ((size_t)nd * 4 + h) * 16 + lane;
            g_xehi[off] = __ushort_as_bfloat16((unsigned short)(b >> 16));
            g_xelo[off] = __float2bfloat16(v - __uint_as_float(b & 0xffff0000u));
        }
    }
}

// ---------------- K2b: x gather + weighted aggregation (minimal regs) ---------
__global__ void __launch_bounds__(256, 3) k_agg(const float* __restrict__ x,
                                                const int* __restrict__ col, int n) {
    __shared__ float s_w[8 * 128];
    __shared__ int   s_c[8 * 32];
    int tid = threadIdx.x, warp = tid >> 5, lane = tid & 31;
    int nd = blockIdx.x * 8 + warp;
    if (nd >= n) return;
    int start = g_rowptr[nd], end = g_rowptr[nd + 1];
    float* swp = s_w + warp * 128;
    int*   scp = s_c + warp * 32;

    float4 acc[4];
#pragma unroll
    for (int h = 0; h < 4; h++) acc[h] = make_float4(0.f, 0.f, 0.f, 0.f);

    for (int base = start; base < end; base += 32) {
        int cnt = min(32, end - base);
        int e2 = base + lane;
        __syncwarp();
        if (e2 < end) {
            scp[lane] = col[e2];
            *(float4*)(swp + lane * 4) = *(const float4*)(g_lg + (size_t)e2 * 4);
        }
        __syncwarp();
#pragma unroll 4
        for (int j = 0; j < cnt; j++) {
            int cj = scp[j];
            float4 wv = *(const float4*)(swp + j * 4);
            float4 xv = *(const float4*)(x + (size_t)cj * 128 + lane * 4);
            acc[0].x += wv.x * xv.x; acc[0].y += wv.x * xv.y; acc[0].z += wv.x * xv.z; acc[0].w += wv.x * xv.w;
            acc[1].x += wv.y * xv.x; acc[1].y += wv.y * xv.y; acc[1].z += wv.y * xv.z; acc[1].w += wv.y * xv.w;
            acc[2].x += wv.z * xv.x; acc[2].y += wv.z * xv.y; acc[2].z += wv.z * xv.z; acc[2].w += wv.z * xv.w;
            acc[3].x += wv.w * xv.x; acc[3].y += wv.w * xv.y; acc[3].z += wv.w * xv.z; acc[3].w += wv.w * xv.w;
        }
    }
#pragma unroll
    for (int h = 0; h < 4; h++) {
        uint32_t h01, h23, l01, l23;
        split4(acc[h], h01, h23, l01, l23);
        size_t off = ((size_t)nd * 4 + h) * 128 + lane * 4;
        *(uint2*)(g_obhi + off) = make_uint2(h01, h23);
        *(uint2*)(g_oblo + off) = make_uint2(l01, l23);
    }
}

// ---------------- K3: MLP layer 1 via mma.sync, streamed buffers --------------
// smem: A[128][280] bf16 (71680 B) + B[64][280] bf16 (35840 B) = 107520 -> 2 CTA/SM
#define SA1 280
#define SMB1 71680
#define MLP1_SMEM 107520
__global__ void __launch_bounds__(256, 2) k_mlp1h(const float* __restrict__ b1, int n) {
    extern __shared__ char smem[];
    uint32_t sb = smem_u32(smem);
    int tid = threadIdx.x, lane = tid & 31, wid = tid >> 5;
    int h = blockIdx.y;
    int n0 = blockIdx.x * 128;

    float c4[2][4][4] = {};
    int wm = wid & 3, wn = wid >> 2;
    uint32_t aB = sb + wm * 32 * (SA1 * 2);
    uint32_t bB = sb + SMB1 + wn * 32 * (SA1 * 2);

    // ---- fill A (hi) + B (hi) ----
    {
        for (int i = tid; i < 128 * 34; i += 256) {
            int r = i / 34, c = i - r * 34;
            int nd = n0 + r;
            uint32_t dst = sb + r * 560 + c * 16;
            if (nd < n) {
                const char* src;
                if (c < 16)      src = (const char*)(g_xhi + (size_t)nd * 128) + c * 16;
                else if (c < 32) src = (const char*)(g_obhi + ((size_t)nd * 4 + h) * 128) + (c - 16) * 16;
                else             src = (const char*)(g_xehi + ((size_t)nd * 4 + h) * 16) + (c - 32) * 16;
                cpa16(dst, src);
            } else {
                *(uint4*)(smem + r * 560 + c * 16) = make_uint4(0, 0, 0, 0);
            }
        }
        const __nv_bfloat16* ws = g_w1s + (size_t)(h * 2 + 0) * OUT_H * F_MLP;
        for (int i = tid; i < 64 * 34; i += 256) {
            int r = i / 34, c = i - r * 34;
            cpa16(sb + SMB1 + r * 560 + c * 16, (const char*)(ws + (size_t)r * F_MLP) + c * 16);
        }
        CPWAIT();
        __syncthreads();
    }
    mma_block<17, SA1, SA1>(c4, aB, bB, lane);      // A_hi * B_hi
    __syncthreads();
    // ---- refill B (lo) ----
    {
        const __nv_bfloat16* ws = g_w1s + (size_t)(h * 2 + 1) * OUT_H * F_MLP;
        for (int i = tid; i < 64 * 34; i += 256) {
            int r = i / 34, c = i - r * 34;
            cpa16(sb + SMB1 + r * 560 + c * 16, (const char*)(ws + (size_t)r * F_MLP) + c * 16);
        }
        CPWAIT();
        __syncthreads();
    }
    mma_block<17, SA1, SA1>(c4, aB, bB, lane);      // A_hi * B_lo
    __syncthreads();
    // ---- refill A (lo) + B (hi) ----
    {
        for (int i = tid; i < 128 * 34; i += 256) {
            int r = i / 34, c = i - r * 34;
            int nd = n0 + r;
            uint32_t dst = sb + r * 560 + c * 16;
            if (nd < n) {
                const char* src;
                if (c < 16)      src = (const char*)(g_xlo + (size_t)nd * 128) + c * 16;
                else if (c < 32) src = (const char*)(g_oblo + ((size_t)nd * 4 + h) * 128) + (c - 16) * 16;
                else             src = (const char*)(g_xelo + ((size_t)nd * 4 + h) * 16) + (c - 32) * 16;
                cpa16(dst, src);
            } else {
                *(uint4*)(smem + r * 560 + c * 16) = make_uint4(0, 0, 0, 0);
            }
        }
        const __nv_bfloat16* ws = g_w1s + (size_t)(h * 2 + 0) * OUT_H * F_MLP;
        for (int i = tid; i < 64 * 34; i += 256) {
            int r = i / 34, c = i - r * 34;
            cpa16(sb + SMB1 + r * 560 + c * 16, (const char*)(ws + (size_t)r * F_MLP) + c * 16);
        }
        CPWAIT();
        __syncthreads();
    }
    mma_block<17, SA1, SA1>(c4, aB, bB, lane);      // A_lo * B_hi

    // ---- epilogue: bias + ReLU -> g_h1, BN partial stats via shfl ----
    const float* bb = b1 + h * 64;
    int g = lane >> 2, tc2 = 2 * (lane & 3);
    float st_s[4][2] = {}, st_q[4][2] = {};
#pragma unroll
    for (int mi = 0; mi < 2; mi++) {
#pragma unroll
        for (int ni = 0; ni < 4; ni++) {
            int colo = wn * 32 + ni * 8 + tc2;
            float2 bv = *(const float2*)(bb + colo);
            int ndr = n0 + wm * 32 + mi * 16 + g;
            float* dst = g_h1 + (size_t)ndr * 256 + h * 64 + colo;
            float v0 = 0.f, v1 = 0.f, v2 = 0.f, v3 = 0.f;
            if (ndr < n) {
                v0 = fmaxf(c4[mi][ni][0] + bv.x, 0.f);
                v1 = fmaxf(c4[mi][ni][1] + bv.y, 0.f);
                *(float2*)dst = make_float2(v0, v1);
            }
            if (ndr + 8 < n) {
                v2 = fmaxf(c4[mi][ni][2] + bv.x, 0.f);
                v3 = fmaxf(c4[mi][ni][3] + bv.y, 0.f);
                *(float2*)(dst + 8 * 256) = make_float2(v2, v3);
            }
            st_s[ni][0] += v0 + v2; st_s[ni][1] += v1 + v3;
            st_q[ni][0] += v0 * v0 + v2 * v2; st_q[ni][1] += v1 * v1 + v3 * v3;
        }
    }
#pragma unroll
    for (int off = 4; off <= 16; off <<= 1) {
#pragma unroll
        for (int ni = 0; ni < 4; ni++) {
#pragma unroll
            for (int cc = 0; cc < 2; cc++) {
                st_s[ni][cc] += __shfl_xor_sync(0xffffffffu, st_s[ni][cc], off);
                st_q[ni][cc] += __shfl_xor_sync(0xffffffffu, st_q[ni][cc], off);
            }
        }
    }
    if (lane < 4) {
#pragma unroll
        for (int ni = 0; ni < 4; ni++) {
            int colo = wn * 32 + ni * 8 + 2 * lane;
            atomicAdd(&g_sum[h * 64 + colo],     st_s[ni][0]);
            atomicAdd(&g_sum[h * 64 + colo + 1], st_s[ni][1]);
            atomicAdd(&g_sqsum[h * 64 + colo],     st_q[ni][0]);
            atomicAdd(&g_sqsum[h * 64 + colo + 1], st_q[ni][1]);
        }
    }
}

// ---------------- K4: finalize BN stats ---------------------------------------
__global__ void k_stats(const float* __restrict__ gamma, const float* __restrict__ beta, int n) {
    int i = threadIdx.x;   // 256
    float inv_n = 1.f / (float)n;
    float mu = g_sum[i] * inv_n;
    float var = g_sqsum[i] * inv_n - mu * mu;
    float r = rsqrtf(var + 1e-5f);
    float a = r * gamma[i];
    g_a[i] = a;
    g_c[i] = beta[i] - mu * a;
}

// ---------------- K5: BN apply + MLP layer 2 via mma.sync ---------------------
#define SA2 72
#define A2HI 0
#define A2LO (128 * SA2 * 2)                 // 18432
#define B2HI (2 * 128 * SA2 * 2)             // 36864
#define B2LO (B2HI + 64 * SA2 * 2)           // 46080
#define MLP2_SMEM (B2LO + 64 * SA2 * 2)      // 55296
__global__ void __launch_bounds__(256) k_mlp2h(const float* __restrict__ b2,
                                               float* __restrict__ out, int n) {
    extern __shared__ char smem[];
    uint32_t sb = smem_u32(smem);
    int tid = threadIdx.x, lane = tid & 31, wid = tid >> 5;
    int h = blockIdx.y;
    int n0 = blockIdx.x * 128;

    // fill B hi/lo via cp.async from pre-split w2
    {
        const char* wh = (const char*)(g_w2s + (size_t)(h * 2 + 0) * OUT_H * 64);
        const char* wl = (const char*)(g_w2s + (size_t)(h * 2 + 1) * OUT_H * 64);
        for (int i = tid; i < 64 * 8; i += 256) {
            int r = i >> 3, c = i & 7;
            cpa16(sb + B2HI + r * 144 + c * 16, wh + (size_t)r * 128 + c * 16);
            cpa16(sb + B2LO + r * 144 + c * 16, wl + (size_t)r * 128 + c * 16);
        }
    }
    // fill A: BN-applied h1 (inline split; K=64 only)
    for (int i = tid; i < 128 * 16; i += 256) {
        int nl = i >> 4, f = (i & 15) * 4;
        int nd = n0 + nl;
        float4 v = make_float4(0.f, 0.f, 0.f, 0.f);
        if (nd < n) {
            float4 hv = *(const float4*)(g_h1 + (size_t)nd * 256 + h * 64 + f);
            float4 av = *(const float4*)(g_a + h * 64 + f);
            float4 cv = *(const float4*)(g_c + h * 64 + f);
            v = make_float4(hv.x * av.x + cv.x, hv.y * av.y + cv.y,
                            hv.z * av.z + cv.z, hv.w * av.w + cv.w);
        }
        uint32_t h01, h23, l01, l23;
        split4(v, h01, h23, l01, l23);
        *(uint2*)(smem + A2HI + (nl * SA2 + f) * 2) = make_uint2(h01, h23);
        *(uint2*)(smem + A2LO + (nl * SA2 + f) * 2) = make_uint2(l01, l23);
    }
    CPWAIT();
    __syncthreads();

    float c4[2][4][4] = {};
    int wm = wid & 3, wn = wid >> 2;
    uint32_t aH = sb + A2HI + wm * 32 * SA2 * 2;
    uint32_t aL = sb + A2LO + wm * 32 * SA2 * 2;
    uint32_t bH = sb + B2HI + wn * 32 * SA2 * 2;
    uint32_t bL = sb + B2LO + wn * 32 * SA2 * 2;
    mma_block<4, SA2, SA2>(c4, aH, bH, lane);
    mma_block<4, SA2, SA2>(c4, aH, bL, lane);
    mma_block<4, SA2, SA2>(c4, aL, bH, lane);

    // epilogue: bias -> out
    const float* bb = b2 + h * 64;
    int g = lane >> 2, tc2 = 2 * (lane & 3);
#pragma unroll
    for (int mi = 0; mi < 2; mi++) {
#pragma unroll
        for (int ni = 0; ni < 4; ni++) {
            int colo = wn * 32 + ni * 8 + tc2;
            float2 bv = *(const float2*)(bb + colo);
            int ndr = n0 + wm * 32 + mi * 16 + g;
            float* dst = out + (size_t)ndr * 256 + h * 64 + colo;
            if (ndr < n)
                *(float2*)dst = make_float2(c4[mi][ni][0] + bv.x, c4[mi][ni][1] + bv.y);
            if (ndr + 8 < n)
                *(float2*)(dst + 8 * 256) =
                    make_float2(c4[mi][ni][2] + bv.x, c4[mi][ni][3] + bv.y);
        }
    }
}

// ---------------- launch ------------------------------------------------------
extern "C" void kernel_launch(void* const* d_in, const int* in_sizes, int n_in,
                              void* d_out, int out_size) {
    const float* x     = (const float*)d_in[0];
    const int*   row   = (const int*)d_in[1];
    const int*   col   = (const int*)d_in[2];
    const float* ea    = (const float*)d_in[3];
    const float* a1w   = (const float*)d_in[4];
    const float* a2w   = (const float*)d_in[5];
    const float* aew   = (const float*)d_in[6];
    const float* w1    = (const float*)d_in[7];
    const float* b1    = (const float*)d_in[8];
    const float* gamma = (const float*)d_in[9];
    const float* beta  = (const float*)d_in[10];
    const float* w2    = (const float*)d_in[11];
    const float* b2    = (const float*)d_in[12];
    float* out = (float*)d_out;

    int n = in_sizes[0] / IN_DIM;
    int e = in_sizes[1];

    cudaFuncSetAttribute(k_mlp1h, cudaFuncAttributeMaxDynamicSharedMemorySize, MLP1_SMEM);
    cudaFuncSetAttribute(k_mlp2h, cudaFuncAttributeMaxDynamicSharedMemorySize, MLP2_SMEM);

    k_rowptr<<<(n + 256) / 256, 256>>>(row, n, e);
    k_nodelogits<<<(n + 7) / 8, 256>>>(x, a1w, a2w, n);
    k_pre<<<4, 256>>>(w1, w2);
    k_attn<<<(n + 7) / 8, 256>>>(col, ea, aew, n);
    k_agg<<<(n + 7) / 8, 256>>>(x, col, n);
    dim3 g3((n + 127) / 128, 4);
    k_mlp1h<<<g3, 256, MLP1_SMEM>>>(b1, n);
    k_stats<<<1, 256>>>(gamma, beta, n);
    k_mlp2h<<<g3, 256, MLP2_SMEM>>>(b2, out, n);
}

// round 15
// speedup vs baseline: 1.4093x; 1.0565x over previous
#include <cuda_runtime.h>
#include <cuda_bf16.h>
#include <math_constants.h>
#include <cstdint>

#define MAXN 100000
#define MAXE 1600000
#define IN_DIM 128
#define EDGE_DIM 16
#define NH 4
#define OUT_H 64
#define F_MLP 272   // 2*128+16

// ---------------- device scratch ----------------------------------------------
__device__ int   g_rowptr[MAXN + 1];
__device__ float g_attn12[(size_t)MAXN * 8];
__device__ float g_lg[(size_t)MAXE * 4];               // logits then final weights
__device__ float g_h1[(size_t)MAXN * NH * OUT_H];      // [n][h][64] = [n][256]
__device__ float g_sum[NH * OUT_H];
__device__ float g_sqsum[NH * OUT_H];
__device__ float g_a[NH * OUT_H];
__device__ float g_c[NH * OUT_H];
// bf16 hi/lo pre-split data
__device__ __nv_bfloat16 g_xhi[(size_t)MAXN * 128];
__device__ __nv_bfloat16 g_xlo[(size_t)MAXN * 128];
__device__ __nv_bfloat16 g_obhi[(size_t)MAXN * NH * 128];
__device__ __nv_bfloat16 g_oblo[(size_t)MAXN * NH * 128];
__device__ __nv_bfloat16 g_xehi[(size_t)MAXN * NH * 16];
__device__ __nv_bfloat16 g_xelo[(size_t)MAXN * NH * 16];
__device__ __nv_bfloat16 g_w1s[(size_t)NH * 2 * OUT_H * F_MLP];  // [h][pass][o][272]
__device__ __nv_bfloat16 g_w2s[(size_t)NH * 2 * OUT_H * OUT_H];  // [h][pass][p][64]

// ---------------- helpers ------------------------------------------------------
__device__ __forceinline__ uint32_t smem_u32(const void* p) {
    uint32_t a;
    asm("{ .reg .u64 t; cvta.to.shared.u64 t, %1; cvt.u32.u64 %0, t; }" : "=r"(a) : "l"(p));
    return a;
}
__device__ __forceinline__ void cpa16(uint32_t dst, const void* src) {
    asm volatile("cp.async.cg.shared.global [%0], [%1], 16;" :: "r"(dst), "l"(src));
}
#define CPWAIT() asm volatile("cp.async.commit_group;\n\tcp.async.wait_group 0;" ::: "memory")

__device__ __forceinline__ void ldsm4(uint32_t* r, uint32_t a) {
    asm volatile("ldmatrix.sync.aligned.m8n8.x4.shared.b16 {%0,%1,%2,%3}, [%4];"
        : "=r"(r[0]), "=r"(r[1]), "=r"(r[2]), "=r"(r[3]) : "r"(a));
}
__device__ __forceinline__ void ldsm2(uint32_t* r, uint32_t a) {
    asm volatile("ldmatrix.sync.aligned.m8n8.x2.shared.b16 {%0,%1}, [%2];"
        : "=r"(r[0]), "=r"(r[1]) : "r"(a));
}
__device__ __forceinline__ void mma_bf16(float* c, const uint32_t* a,
                                         uint32_t b0, uint32_t b1) {
    asm volatile("mma.sync.aligned.m16n8k16.row.col.f32.bf16.bf16.f32 "
        "{%0,%1,%2,%3}, {%4,%5,%6,%7}, {%8,%9}, {%0,%1,%2,%3};"
        : "+f"(c[0]), "+f"(c[1]), "+f"(c[2]), "+f"(c[3])
        : "r"(a[0]), "r"(a[1]), "r"(a[2]), "r"(a[3]), "r"(b0), "r"(b1));
}

template<int KSTEPS, int SA, int SB>
__device__ __forceinline__ void mma_block(float c[2][4][4], uint32_t aBase,
                                          uint32_t bBase, int lane) {
    uint32_t aRow = aBase + (uint32_t)(((lane & 15) * SA + ((lane >> 4) << 3)) * 2);
    uint32_t bRow = bBase + (uint32_t)(((lane & 7) * SB + (((lane >> 3) & 1) << 3)) * 2);
#pragma unroll
    for (int ks = 0; ks < KSTEPS; ks++) {
        uint32_t a0[4], a1[4];
        ldsm4(a0, aRow + ks * 32);
        ldsm4(a1, aRow + 16 * SA * 2 + ks * 32);
#pragma unroll
        for (int ni = 0; ni < 4; ni++) {
            uint32_t b[2];
            ldsm2(b, bRow + ni * 8 * SB * 2 + ks * 32);
            mma_bf16(c[0][ni], a0, b[0], b[1]);
            mma_bf16(c[1][ni], a1, b[0], b[1]);
        }
    }
}

// split fp32 float4 -> bf16 hi pair-words + lo pair-words
__device__ __forceinline__ void split4(float4 v, uint32_t& hi01, uint32_t& hi23,
                                       uint32_t& lo01, uint32_t& lo23) {
    uint32_t b0 = __float_as_uint(v.x), b1 = __float_as_uint(v.y);
    uint32_t b2 = __float_as_uint(v.z), b3 = __float_as_uint(v.w);
    hi01 = __byte_perm(b0, b1, 0x7632);
    hi23 = __byte_perm(b2, b3, 0x7632);
    float l0 = v.x - __uint_as_float(b0 & 0xffff0000u);
    float l1 = v.y - __uint_as_float(b1 & 0xffff0000u);
    float l2 = v.z - __uint_as_float(b2 & 0xffff0000u);
    float l3 = v.w - __uint_as_float(b3 & 0xffff0000u);
    __nv_bfloat162 p01 = __floats2bfloat162_rn(l0, l1);
    __nv_bfloat162 p23 = __floats2bfloat162_rn(l2, l3);
    lo01 = *reinterpret_cast<uint32_t*>(&p01);
    lo23 = *reinterpret_cast<uint32_t*>(&p23);
}

// ---------------- K0: CSR row pointers ----------------------------------------
__global__ void k_rowptr(const int* __restrict__ row, int n, int e) {
    int i = blockIdx.x * blockDim.x + threadIdx.x;
    if (i > n) return;
    int lo = 0, hi = e;
    while (lo < hi) { int mid = (lo + hi) >> 1; if (row[mid] < i) lo = mid + 1; else hi = mid; }
    g_rowptr[i] = lo;
}

// ---------------- K1: per-node attention logits + x hi/lo split ---------------
__global__ void k_nodelogits(const float* __restrict__ x, const float* __restrict__ a1w,
                             const float* __restrict__ a2w, int n) {
    __shared__ float sw[8 * 128];
    int tid = threadIdx.x;
    for (int i = tid; i < 512; i += 256) { sw[i] = a1w[i]; sw[512 + i] = a2w[i]; }
    __syncthreads();
    int warp = tid >> 5, lane = tid & 31;
    int nd = blockIdx.x * 8 + warp;
    if (nd >= n) return;
    float4 xv = *(const float4*)(x + (size_t)nd * 128 + lane * 4);
    // fused x split
    {
        uint32_t h01, h23, l01, l23;
        split4(xv, h01, h23, l01, l23);
        *(uint2*)(g_xhi + (size_t)nd * 128 + lane * 4) = make_uint2(h01, h23);
        *(uint2*)(g_xlo + (size_t)nd * 128 + lane * 4) = make_uint2(l01, l23);
    }
#pragma unroll
    for (int k = 0; k < 8; k++) {
        float4 wv = *(const float4*)(sw + k * 128 + lane * 4);
        float p = xv.x * wv.x + xv.y * wv.y + xv.z * wv.z + xv.w * wv.w;
        p += __shfl_xor_sync(0xffffffffu, p, 16);
        p += __shfl_xor_sync(0xffffffffu, p, 8);
        p += __shfl_xor_sync(0xffffffffu, p, 4);
        p += __shfl_xor_sync(0xffffffffu, p, 2);
        p += __shfl_xor_sync(0xffffffffu, p, 1);
        if (lane == 0) g_attn12[(size_t)nd * 8 + k] = p;
    }
}

// ---------------- K_pre: pre-split w1/w2 to bf16 hi/lo; zero stats ------------
__global__ void k_pre(const float* __restrict__ w1, const float* __restrict__ w2) {
    int h = blockIdx.x, tid = threadIdx.x;   // 4 blocks x 256
    for (int i = tid; i < OUT_H * 68; i += 256) {
        int o = i / 68, f = (i - o * 68) * 4;
        float4 v = *(const float4*)(w1 + ((size_t)h * OUT_H + o) * F_MLP + f);
        uint32_t h01, h23, l01, l23;
        split4(v, h01, h23, l01, l23);
        *(uint2*)(g_w1s + ((size_t)(h * 2 + 0) * OUT_H + o) * F_MLP + f) = make_uint2(h01, h23);
        *(uint2*)(g_w1s + ((size_t)(h * 2 + 1) * OUT_H + o) * F_MLP + f) = make_uint2(l01, l23);
    }
    for (int i = tid; i < OUT_H * 16; i += 256) {
        int p = i >> 4, f = (i & 15) * 4;
        float4 v = *(const float4*)(w2 + (size_t)h * 4096 + p * 64 + f);
        uint32_t h01, h23, l01, l23;
        split4(v, h01, h23, l01, l23);
        *(uint2*)(g_w2s + ((size_t)(h * 2 + 0) * OUT_H + p) * 64 + f) = make_uint2(h01, h23);
        *(uint2*)(g_w2s + ((size_t)(h * 2 + 1) * OUT_H + p) * 64 + f) = make_uint2(l01, l23);
    }
    if (h == 0) { g_sum[tid] = 0.f; g_sqsum[tid] = 0.f; }
}

// ---------------- shared logits helper -----------------------------------------
__device__ __forceinline__ void logits_from_q(float4 q0, float4 q1, float4 q2, float4 q3,
                                              const float* s_aew, int ci,
                                              const float* a1h, float* lg) {
    float4 a2v = *(const float4*)(g_attn12 + (size_t)ci * 8 + 4);
    float a2a[4] = {a2v.x, a2v.y, a2v.z, a2v.w};
#pragma unroll
    for (int h = 0; h < 4; h++) {
        const float* wq = s_aew + h * 16;
        float d = q0.x * wq[0] + q0.y * wq[1] + q0.z * wq[2] + q0.w * wq[3]
                + q1.x * wq[4] + q1.y * wq[5] + q1.z * wq[6] + q1.w * wq[7]
                + q2.x * wq[8] + q2.y * wq[9] + q2.z * wq[10] + q2.w * wq[11]
                + q3.x * wq[12] + q3.y * wq[13] + q3.z * wq[14] + q3.w * wq[15];
        lg[h] = (a1h[h] + a2a[h] + d) * 0.125f;
    }
}

// ---------------- K2a: attention softmax + xe aggregation (deg<=32 only) ------
__global__ void __launch_bounds__(256, 3) k_attn(const int* __restrict__ col,
                                                 const float* __restrict__ ea,
                                                 const float* __restrict__ aew, int n) {
    __shared__ float s_aew[64];
    __shared__ float s_ea[8 * 32 * 16];   // [warp][edge][16] 16KB
    __shared__ float s_w[8 * 128];        // [warp][edge][4]
    int tid = threadIdx.x;
    if (tid < 64) s_aew[tid] = aew[tid];
    __syncthreads();
    int warp = tid >> 5, lane = tid & 31;
    int nd = blockIdx.x * 8 + warp;
    if (nd >= n) return;
    int start = g_rowptr[nd], end = g_rowptr[nd + 1];
    int deg = end - start;
    if (deg > 32) return;                 // handled by k_attn_big
    float a1h[4];
    {
        float4 a1v = *(const float4*)(g_attn12 + (size_t)nd * 8);
        a1h[0] = a1v.x; a1h[1] = a1v.y; a1h[2] = a1v.z; a1h[3] = a1v.w;
    }
    float* eap = s_ea + warp * 512;
    float* swp = s_w + warp * 128;

    int e2 = start + lane;
    bool have = (e2 < end);
    float lg[4] = {-CUDART_INF_F, -CUDART_INF_F, -CUDART_INF_F, -CUDART_INF_F};
    if (have) {
        int ci = col[e2];
        const float4* ep = (const float4*)(ea + (size_t)e2 * 16);
        float4 q0 = ep[0], q1 = ep[1], q2 = ep[2], q3 = ep[3];
        *(float4*)(eap + lane * 16 + 0)  = q0;
        *(float4*)(eap + lane * 16 + 4)  = q1;
        *(float4*)(eap + lane * 16 + 8)  = q2;
        *(float4*)(eap + lane * 16 + 12) = q3;
        logits_from_q(q0, q1, q2, q3, s_aew, ci, a1h, lg);
    }
    float w[4];
#pragma unroll
    for (int h = 0; h < 4; h++) {
        float mm = lg[h];
#pragma unroll
        for (int off = 16; off >= 1; off >>= 1)
            mm = fmaxf(mm, __shfl_xor_sync(0xffffffffu, mm, off));
        float ex = have ? __expf(lg[h] - mm) : 0.f;
        float ssum = ex;
#pragma unroll
        for (int off = 16; off >= 1; off >>= 1)
            ssum += __shfl_xor_sync(0xffffffffu, ssum, off);
        w[h] = ex / (ssum + 1e-16f);
    }
    if (have) {
        *(float4*)(swp + lane * 4) = make_float4(w[0], w[1], w[2], w[3]);
        *(float4*)(g_lg + (size_t)e2 * 4) = make_float4(w[0], w[1], w[2], w[3]);
    }
    __syncwarp();
    // xe aggregation: full warp — lane = (half, d); halves take alternating edges
    float acce[4] = {0.f, 0.f, 0.f, 0.f};
    {
        int d = lane & 15, half = lane >> 4;
        for (int j = half; j < deg; j += 2) {
            float4 wv = *(const float4*)(swp + j * 4);
            float eav = eap[j * 16 + d];
            acce[0] += wv.x * eav; acce[1] += wv.y * eav;
            acce[2] += wv.z * eav; acce[3] += wv.w * eav;
        }
#pragma unroll
        for (int h = 0; h < 4; h++)
            acce[h] += __shfl_xor_sync(0xffffffffu, acce[h], 16);
    }
    if (lane < 16) {
#pragma unroll
        for (int h = 0; h < 4; h++) {
            float v = acce[h];
            uint32_t b = __float_as_uint(v);
            size_t off = ((size_t)nd * 4 + h) * 16 + lane;
            g_xehi[off] = __ushort_as_bfloat16((unsigned short)(b >> 16));
            g_xelo[off] = __float2bfloat16(v - __uint_as_float(b & 0xffff0000u));
        }
    }
}

// ---------------- K2a': general path for deg>32 (rare) ------------------------
__global__ void __launch_bounds__(256) k_attn_big(const int* __restrict__ col,
                                                  const float* __restrict__ ea,
                                                  const float* __restrict__ aew, int n) {
    __shared__ float s_aew[64];
    __shared__ float s_ea[8 * 32 * 16];
    __shared__ float s_w[8 * 128];
    int tid = threadIdx.x;
    if (tid < 64) s_aew[tid] = aew[tid];
    __syncthreads();
    int warp = tid >> 5, lane = tid & 31;
    int nd = blockIdx.x * 8 + warp;
    if (nd >= n) return;
    int start = g_rowptr[nd], end = g_rowptr[nd + 1];
    int deg = end - start;
    if (deg <= 32) return;                // handled by k_attn
    float a1h[4];
    {
        float4 a1v = *(const float4*)(g_attn12 + (size_t)nd * 8);
        a1h[0] = a1v.x; a1h[1] = a1v.y; a1h[2] = a1v.z; a1h[3] = a1v.w;
    }
    float* eap = s_ea + warp * 512;
    float* swp = s_w + warp * 128;
    float acce[4] = {0.f, 0.f, 0.f, 0.f};

    float mm[4] = {-CUDART_INF_F, -CUDART_INF_F, -CUDART_INF_F, -CUDART_INF_F};
    float s[4] = {0.f, 0.f, 0.f, 0.f};
    for (int base = start; base < end; base += 32) {
        int e2 = base + lane;
        if (e2 < end) {
            int ci = col[e2];
            const float4* ep = (const float4*)(ea + (size_t)e2 * 16);
            float lg[4];
            logits_from_q(ep[0], ep[1], ep[2], ep[3], s_aew, ci, a1h, lg);
            *(float4*)(g_lg + (size_t)e2 * 4) = make_float4(lg[0], lg[1], lg[2], lg[3]);
#pragma unroll
            for (int h = 0; h < 4; h++) {
                if (lg[h] > mm[h]) { s[h] = s[h] * __expf(mm[h] - lg[h]) + 1.f; mm[h] = lg[h]; }
                else               { s[h] += __expf(lg[h] - mm[h]); }
            }
        }
    }
#pragma unroll
    for (int off = 16; off >= 1; off >>= 1) {
#pragma unroll
        for (int h = 0; h < 4; h++) {
            float om = __shfl_xor_sync(0xffffffffu, mm[h], off);
            float os = __shfl_xor_sync(0xffffffffu, s[h], off);
            float nm = fmaxf(mm[h], om);
            float t = (s[h] > 0.f ? s[h] * __expf(mm[h] - nm) : 0.f)
                    + (os > 0.f ? os * __expf(om - nm) : 0.f);
            mm[h] = nm; s[h] = t;
        }
    }
    float inv[4];
#pragma unroll
    for (int h = 0; h < 4; h++) inv[h] = 1.f / (s[h] + 1e-16f);
    for (int base = start; base < end; base += 32) {
        int cnt = min(32, end - base);
        int e2 = base + lane;
        __syncwarp();
        if (e2 < end) {
            float4 lgv = *(const float4*)(g_lg + (size_t)e2 * 4);
            float4 wv = make_float4(__expf(lgv.x - mm[0]) * inv[0],
                                    __expf(lgv.y - mm[1]) * inv[1],
                                    __expf(lgv.z - mm[2]) * inv[2],
                                    __expf(lgv.w - mm[3]) * inv[3]);
            *(float4*)(g_lg + (size_t)e2 * 4) = wv;
            *(float4*)(swp + lane * 4) = wv;
            const float4* ep = (const float4*)(ea + (size_t)e2 * 16);
            *(float4*)(eap + lane * 16 + 0)  = ep[0];
            *(float4*)(eap + lane * 16 + 4)  = ep[1];
            *(float4*)(eap + lane * 16 + 8)  = ep[2];
            *(float4*)(eap + lane * 16 + 12) = ep[3];
        }
        __syncwarp();
        if (lane < 16) {
            for (int j = 0; j < cnt; j++) {
                float4 wv = *(const float4*)(swp + j * 4);
                float eav = eap[j * 16 + lane];
                acce[0] += wv.x * eav; acce[1] += wv.y * eav;
                acce[2] += wv.z * eav; acce[3] += wv.w * eav;
            }
        }
    }
    if (lane < 16) {
#pragma unroll
        for (int h = 0; h < 4; h++) {
            float v = acce[h];
            uint32_t b = __float_as_uint(v);
            size_t off = ((size_t)nd * 4 + h) * 16 + lane;
            g_xehi[off] = __ushort_as_bfloat16((unsigned short)(b >> 16));
            g_xelo[off] = __float2bfloat16(v - __uint_as_float(b & 0xffff0000u));
        }
    }
}

// ---------------- K2b: x gather + weighted aggregation (minimal regs) ---------
__global__ void __launch_bounds__(256, 3) k_agg(const float* __restrict__ x,
                                                const int* __restrict__ col, int n) {
    __shared__ float s_w[8 * 128];
    __shared__ int   s_c[8 * 32];
    int tid = threadIdx.x, warp = tid >> 5, lane = tid & 31;
    int nd = blockIdx.x * 8 + warp;
    if (nd >= n) return;
    int start = g_rowptr[nd], end = g_rowptr[nd + 1];
    float* swp = s_w + warp * 128;
    int*   scp = s_c + warp * 32;

    float4 acc[4];
#pragma unroll
    for (int h = 0; h < 4; h++) acc[h] = make_float4(0.f, 0.f, 0.f, 0.f);

    for (int base = start; base < end; base += 32) {
        int cnt = min(32, end - base);
        int e2 = base + lane;
        __syncwarp();
        if (e2 < end) {
            scp[lane] = col[e2];
            *(float4*)(swp + lane * 4) = *(const float4*)(g_lg + (size_t)e2 * 4);
        }
        __syncwarp();
#pragma unroll 4
        for (int j = 0; j < cnt; j++) {
            int cj = scp[j];
            float4 wv = *(const float4*)(swp + j * 4);
            float4 xv = *(const float4*)(x + (size_t)cj * 128 + lane * 4);
            acc[0].x += wv.x * xv.x; acc[0].y += wv.x * xv.y; acc[0].z += wv.x * xv.z; acc[0].w += wv.x * xv.w;
            acc[1].x += wv.y * xv.x; acc[1].y += wv.y * xv.y; acc[1].z += wv.y * xv.z; acc[1].w += wv.y * xv.w;
            acc[2].x += wv.z * xv.x; acc[2].y += wv.z * xv.y; acc[2].z += wv.z * xv.z; acc[2].w += wv.z * xv.w;
            acc[3].x += wv.w * xv.x; acc[3].y += wv.w * xv.y; acc[3].z += wv.w * xv.z; acc[3].w += wv.w * xv.w;
        }
    }
#pragma unroll
    for (int h = 0; h < 4; h++) {
        uint32_t h01, h23, l01, l23;
        split4(acc[h], h01, h23, l01, l23);
        size_t off = ((size_t)nd * 4 + h) * 128 + lane * 4;
        *(uint2*)(g_obhi + off) = make_uint2(h01, h23);
        *(uint2*)(g_oblo + off) = make_uint2(l01, l23);
    }
}

// ---------------- K3: MLP layer 1 via mma.sync, streamed buffers --------------
// smem: A[128][280] bf16 (71680 B) + B[64][280] bf16 (35840 B) = 107520 -> 2 CTA/SM
#define SA1 280
#define SMB1 71680
#define MLP1_SMEM 107520
__global__ void __launch_bounds__(256, 2) k_mlp1h(const float* __restrict__ b1, int n) {
    extern __shared__ char smem[];
    uint32_t sb = smem_u32(smem);
    int tid = threadIdx.x, lane = tid & 31, wid = tid >> 5;
    int h = blockIdx.y;
    int n0 = blockIdx.x * 128;

    float c4[2][4][4] = {};
    int wm = wid & 3, wn = wid >> 2;
    uint32_t aB = sb + wm * 32 * (SA1 * 2);
    uint32_t bB = sb + SMB1 + wn * 32 * (SA1 * 2);

    // ---- fill A (hi) + B (hi) ----
    {
        for (int i = tid; i < 128 * 34; i += 256) {
            int r = i / 34, c = i - r * 34;
            int nd = n0 + r;
            uint32_t dst = sb + r * 560 + c * 16;
            if (nd < n) {
                const char* src;
                if (c < 16)      src = (const char*)(g_xhi + (size_t)nd * 128) + c * 16;
                else if (c < 32) src = (const char*)(g_obhi + ((size_t)nd * 4 + h) * 128) + (c - 16) * 16;
                else             src = (const char*)(g_xehi + ((size_t)nd * 4 + h) * 16) + (c - 32) * 16;
                cpa16(dst, src);
            } else {
                *(uint4*)(smem + r * 560 + c * 16) = make_uint4(0, 0, 0, 0);
            }
        }
        const __nv_bfloat16* ws = g_w1s + (size_t)(h * 2 + 0) * OUT_H * F_MLP;
        for (int i = tid; i < 64 * 34; i += 256) {
            int r = i / 34, c = i - r * 34;
            cpa16(sb + SMB1 + r * 560 + c * 16, (const char*)(ws + (size_t)r * F_MLP) + c * 16);
        }
        CPWAIT();
        __syncthreads();
    }
    mma_block<17, SA1, SA1>(c4, aB, bB, lane);      // A_hi * B_hi
    __syncthreads();
    // ---- refill B (lo) ----
    {
        const __nv_bfloat16* ws = g_w1s + (size_t)(h * 2 + 1) * OUT_H * F_MLP;
        for (int i = tid; i < 64 * 34; i += 256) {
            int r = i / 34, c = i - r * 34;
            cpa16(sb + SMB1 + r * 560 + c * 16, (const char*)(ws + (size_t)r * F_MLP) + c * 16);
        }
        CPWAIT();
        __syncthreads();
    }
    mma_block<17, SA1, SA1>(c4, aB, bB, lane);      // A_hi * B_lo
    __syncthreads();
    // ---- refill A (lo) + B (hi) ----
    {
        for (int i = tid; i < 128 * 34; i += 256) {
            int r = i / 34, c = i - r * 34;
            int nd = n0 + r;
            uint32_t dst = sb + r * 560 + c * 16;
            if (nd < n) {
                const char* src;
                if (c < 16)      src = (const char*)(g_xlo + (size_t)nd * 128) + c * 16;
                else if (c < 32) src = (const char*)(g_oblo + ((size_t)nd * 4 + h) * 128) + (c - 16) * 16;
                else             src = (const char*)(g_xelo + ((size_t)nd * 4 + h) * 16) + (c - 32) * 16;
                cpa16(dst, src);
            } else {
                *(uint4*)(smem + r * 560 + c * 16) = make_uint4(0, 0, 0, 0);
            }
        }
        const __nv_bfloat16* ws = g_w1s + (size_t)(h * 2 + 0) * OUT_H * F_MLP;
        for (int i = tid; i < 64 * 34; i += 256) {
            int r = i / 34, c = i - r * 34;
            cpa16(sb + SMB1 + r * 560 + c * 16, (const char*)(ws + (size_t)r * F_MLP) + c * 16);
        }
        CPWAIT();
        __syncthreads();
    }
    mma_block<17, SA1, SA1>(c4, aB, bB, lane);      // A_lo * B_hi

    // ---- epilogue: bias + ReLU -> g_h1, BN partial stats via shfl ----
    const float* bb = b1 + h * 64;
    int g = lane >> 2, tc2 = 2 * (lane & 3);
    float st_s[4][2] = {}, st_q[4][2] = {};
#pragma unroll
    for (int mi = 0; mi < 2; mi++) {
#pragma unroll
        for (int ni = 0; ni < 4; ni++) {
            int colo = wn * 32 + ni * 8 + tc2;
            float2 bv = *(const float2*)(bb + colo);
            int ndr = n0 + wm * 32 + mi * 16 + g;
            float* dst = g_h1 + (size_t)ndr * 256 + h * 64 + colo;
            float v0 = 0.f, v1 = 0.f, v2 = 0.f, v3 = 0.f;
            if (ndr < n) {
                v0 = fmaxf(c4[mi][ni][0] + bv.x, 0.f);
                v1 = fmaxf(c4[mi][ni][1] + bv.y, 0.f);
                *(float2*)dst = make_float2(v0, v1);
            }
            if (ndr + 8 < n) {
                v2 = fmaxf(c4[mi][ni][2] + bv.x, 0.f);
                v3 = fmaxf(c4[mi][ni][3] + bv.y, 0.f);
                *(float2*)(dst + 8 * 256) = make_float2(v2, v3);
            }
            st_s[ni][0] += v0 + v2; st_s[ni][1] += v1 + v3;
            st_q[ni][0] += v0 * v0 + v2 * v2; st_q[ni][1] += v1 * v1 + v3 * v3;
        }
    }
#pragma unroll
    for (int off = 4; off <= 16; off <<= 1) {
#pragma unroll
        for (int ni = 0; ni < 4; ni++) {
#pragma unroll
            for (int cc = 0; cc < 2; cc++) {
                st_s[ni][cc] += __shfl_xor_sync(0xffffffffu, st_s[ni][cc], off);
                st_q[ni][cc] += __shfl_xor_sync(0xffffffffu, st_q[ni][cc], off);
            }
        }
    }
    if (lane < 4) {
#pragma unroll
        for (int ni = 0; ni < 4; ni++) {
            int colo = wn * 32 + ni * 8 + 2 * lane;
            atomicAdd(&g_sum[h * 64 + colo],     st_s[ni][0]);
            atomicAdd(&g_sum[h * 64 + colo + 1], st_s[ni][1]);
            atomicAdd(&g_sqsum[h * 64 + colo],     st_q[ni][0]);
            atomicAdd(&g_sqsum[h * 64 + colo + 1], st_q[ni][1]);
        }
    }
}

// ---------------- K4: finalize BN stats ---------------------------------------
__global__ void k_stats(const float* __restrict__ gamma, const float* __restrict__ beta, int n) {
    int i = threadIdx.x;   // 256
    float inv_n = 1.f / (float)n;
    float mu = g_sum[i] * inv_n;
    float var = g_sqsum[i] * inv_n - mu * mu;
    float r = rsqrtf(var + 1e-5f);
    float a = r * gamma[i];
    g_a[i] = a;
    g_c[i] = beta[i] - mu * a;
}

// ---------------- K5: BN apply + MLP layer 2 via mma.sync ---------------------
#define SA2 72
#define A2HI 0
#define A2LO (128 * SA2 * 2)                 // 18432
#define B2HI (2 * 128 * SA2 * 2)             // 36864
#define B2LO (B2HI + 64 * SA2 * 2)           // 46080
#define MLP2_SMEM (B2LO + 64 * SA2 * 2)      // 55296
__global__ void __launch_bounds__(256) k_mlp2h(const float* __restrict__ b2,
                                               float* __restrict__ out, int n) {
    extern __shared__ char smem[];
    uint32_t sb = smem_u32(smem);
    int tid = threadIdx.x, lane = tid & 31, wid = tid >> 5;
    int h = blockIdx.y;
    int n0 = blockIdx.x * 128;

    // fill B hi/lo via cp.async from pre-split w2
    {
        const char* wh = (const char*)(g_w2s + (size_t)(h * 2 + 0) * OUT_H * 64);
        const char* wl = (const char*)(g_w2s + (size_t)(h * 2 + 1) * OUT_H * 64);
        for (int i = tid; i < 64 * 8; i += 256) {
            int r = i >> 3, c = i & 7;
            cpa16(sb + B2HI + r * 144 + c * 16, wh + (size_t)r * 128 + c * 16);
            cpa16(sb + B2LO + r * 144 + c * 16, wl + (size_t)r * 128 + c * 16);
        }
    }
    // fill A: BN-applied h1 (inline split; K=64 only)
    for (int i = tid; i < 128 * 16; i += 256) {
        int nl = i >> 4, f = (i & 15) * 4;
        int nd = n0 + nl;
        float4 v = make_float4(0.f, 0.f, 0.f, 0.f);
        if (nd < n) {
            float4 hv = *(const float4*)(g_h1 + (size_t)nd * 256 + h * 64 + f);
            float4 av = *(const float4*)(g_a + h * 64 + f);
            float4 cv = *(const float4*)(g_c + h * 64 + f);
            v = make_float4(hv.x * av.x + cv.x, hv.y * av.y + cv.y,
                            hv.z * av.z + cv.z, hv.w * av.w + cv.w);
        }
        uint32_t h01, h23, l01, l23;
        split4(v, h01, h23, l01, l23);
        *(uint2*)(smem + A2HI + (nl * SA2 + f) * 2) = make_uint2(h01, h23);
        *(uint2*)(smem + A2LO + (nl * SA2 + f) * 2) = make_uint2(l01, l23);
    }
    CPWAIT();
    __syncthreads();

    float c4[2][4][4] = {};
    int wm = wid & 3, wn = wid >> 2;
    uint32_t aH = sb + A2HI + wm * 32 * SA2 * 2;
    uint32_t aL = sb + A2LO + wm * 32 * SA2 * 2;
    uint32_t bH = sb + B2HI + wn * 32 * SA2 * 2;
    uint32_t bL = sb + B2LO + wn * 32 * SA2 * 2;
    mma_block<4, SA2, SA2>(c4, aH, bH, lane);
    mma_block<4, SA2, SA2>(c4, aH, bL, lane);
    mma_block<4, SA2, SA2>(c4, aL, bH, lane);

    // epilogue: bias -> out
    const float* bb = b2 + h * 64;
    int g = lane >> 2, tc2 = 2 * (lane & 3);
#pragma unroll
    for (int mi = 0; mi < 2; mi++) {
#pragma unroll
        for (int ni = 0; ni < 4; ni++) {
            int colo = wn * 32 + ni * 8 + tc2;
            float2 bv = *(const float2*)(bb + colo);
            int ndr = n0 + wm * 32 + mi * 16 + g;
            float* dst = out + (size_t)ndr * 256 + h * 64 + colo;
            if (ndr < n)
                *(float2*)dst = make_float2(c4[mi][ni][0] + bv.x, c4[mi][ni][1] + bv.y);
            if (ndr + 8 < n)
                *(float2*)(dst + 8 * 256) =
                    make_float2(c4[mi][ni][2] + bv.x, c4[mi][ni][3] + bv.y);
        }
    }
}

// ---------------- launch ------------------------------------------------------
extern "C" void kernel_launch(void* const* d_in, const int* in_sizes, int n_in,
                              void* d_out, int out_size) {
    const float* x     = (const float*)d_in[0];
    const int*   row   = (const int*)d_in[1];
    const int*   col   = (const int*)d_in[2];
    const float* ea    = (const float*)d_in[3];
    const float* a1w   = (const float*)d_in[4];
    const float* a2w   = (const float*)d_in[5];
    const float* aew   = (const float*)d_in[6];
    const float* w1    = (const float*)d_in[7];
    const float* b1    = (const float*)d_in[8];
    const float* gamma = (const float*)d_in[9];
    const float* beta  = (const float*)d_in[10];
    const float* w2    = (const float*)d_in[11];
    const float* b2    = (const float*)d_in[12];
    float* out = (float*)d_out;

    int n = in_sizes[0] / IN_DIM;
    int e = in_sizes[1];

    cudaFuncSetAttribute(k_mlp1h, cudaFuncAttributeMaxDynamicSharedMemorySize, MLP1_SMEM);
    cudaFuncSetAttribute(k_mlp2h, cudaFuncAttributeMaxDynamicSharedMemorySize, MLP2_SMEM);

    k_rowptr<<<(n + 256) / 256, 256>>>(row, n, e);
    k_nodelogits<<<(n + 7) / 8, 256>>>(x, a1w, a2w, n);
    k_pre<<<4, 256>>>(w1, w2);
    k_attn<<<(n + 7) / 8, 256>>>(col, ea, aew, n);
    k_attn_big<<<(n + 7) / 8, 256>>>(col, ea, aew, n);
    k_agg<<<(n + 7) / 8, 256>>>(x, col, n);
    dim3 g3((n + 127) / 128, 4);
    k_mlp1h<<<g3, 256, MLP1_SMEM>>>(b1, n);
    k_stats<<<1, 256>>>(gamma, beta, n);
    k_mlp2h<<<g3, 256, MLP2_SMEM>>>(b2, out, n);
}